// round 5
// baseline (speedup 1.0000x reference)
#include <cuda_runtime.h>
#include <stdint.h>
#include <math.h>

// ---------------------------------------------------------------------------
// InformerEncoder: B=4, L0=2048, C=2, D=512, F=512, H=8, dh=64, EL=3
// All math exact fp32 (reference = JAX exact-f32). PE evaluated via double
// transcendentals on fp32 arguments (immune to --use_fast_math). PRNG follows
// jax_threefry_partitionable=True semantics (foldlike split, per-element
// 64-bit counter, 32-bit draw = out0 ^ out1).
// ---------------------------------------------------------------------------
#define D_MODEL 512
#define BATCH   4
#define LMAX    2048
#define NH      8
#define DH      64
#define UMAX    40

#define FLAG_BIAS 1
#define FLAG_RES  2
#define FLAG_GELU 4

// ------------------------- scratch (static device globals) ------------------
__device__ float g_X   [BATCH*LMAX*D_MODEL];
__device__ float g_XN  [BATCH*LMAX*D_MODEL];
__device__ float g_Y   [BATCH*LMAX*D_MODEL];
__device__ float g_Q   [BATCH*LMAX*D_MODEL];
__device__ float g_K   [BATCH*LMAX*D_MODEL];
__device__ float g_V   [BATCH*LMAX*D_MODEL];
__device__ float g_O   [BATCH*LMAX*D_MODEL];
__device__ float g_H1  [BATCH*LMAX*D_MODEL];
__device__ float g_XC  [BATCH*LMAX*3*D_MODEL];
__device__ float g_CV  [BATCH*LMAX*D_MODEL];
__device__ float g_WC  [D_MODEL*3*D_MODEL];
__device__ int   g_IDX [LMAX*UMAX];
__device__ float g_M   [BATCH*NH*LMAX];
__device__ int   g_TOP [BATCH*NH*UMAX];
__device__ float g_VM  [BATCH*NH*DH];

// ------------------------- threefry2x32 (JAX-compatible) --------------------
__host__ __device__ inline void threefry2x32(uint32_t k0, uint32_t k1,
                                             uint32_t x0, uint32_t x1,
                                             uint32_t* o0, uint32_t* o1)
{
    uint32_t ks0 = k0, ks1 = k1, ks2 = k0 ^ k1 ^ 0x1BD11BDAu;
    uint32_t ks[3] = {ks0, ks1, ks2};
    x0 += ks0; x1 += ks1;
    const int rA[4] = {13, 15, 26, 6};
    const int rB[4] = {17, 29, 16, 24};
    #pragma unroll
    for (int g = 0; g < 5; ++g) {
        const int* r = (g & 1) ? rB : rA;
        #pragma unroll
        for (int i = 0; i < 4; ++i) {
            x0 += x1;
            x1 = (x1 << r[i]) | (x1 >> (32 - r[i]));
            x1 ^= x0;
        }
        x0 += ks[(g + 1) % 3];
        x1 += ks[(g + 2) % 3] + (uint32_t)(g + 1);
    }
    *o0 = x0; *o1 = x1;
}

// Partitionable random_bits: element j uses counter (hi=0, lo=j); 32-bit draw
// = out0 ^ out1. idx = bits & (L-1)  (randint span = L is a power of two).
__global__ void idx_kernel(uint32_t k0, uint32_t k1, int n, unsigned mask,
                           int* __restrict__ idx)
{
    int j = blockIdx.x * blockDim.x + threadIdx.x;
    if (j >= n) return;
    uint32_t o0, o1;
    threefry2x32(k0, k1, 0u, (uint32_t)j, &o0, &o1);
    idx[j] = (int)((o0 ^ o1) & mask);
}

// ------------------------- SGEMM (exact fp32) -------------------------------
// C = A @ W^T (+bias)(+R)(gelu). A: MxK row-major, W: NxK row-major.
// BM=BN=128, BK=8, 256 thr, 8x8 microtile.
__device__ __forceinline__ float gelu_exact(float x)
{
    return 0.5f * x * (1.0f + erff(x * 0.70710678118654752f));
}

__global__ __launch_bounds__(256)
void sgemm_kernel(const float* __restrict__ A, const float* __restrict__ W,
                  const float* __restrict__ bias, const float* __restrict__ R,
                  float* __restrict__ C, int N, int K, int flags)
{
    __shared__ float As[8][128];
    __shared__ float Ws[8][128];
    const int t    = threadIdx.x;
    const int tx   = t & 15;
    const int ty   = t >> 4;
    const int lrow = t >> 1;
    const int lseg = (t & 1) << 2;

    const float* Ab = A + (size_t)blockIdx.y * 128 * K;
    const float* Wb = W + (size_t)blockIdx.x * 128 * K;

    float acc[8][8];
    #pragma unroll
    for (int i = 0; i < 8; i++)
        #pragma unroll
        for (int j = 0; j < 8; j++) acc[i][j] = 0.f;

    for (int k0 = 0; k0 < K; k0 += 8) {
        float4 a4 = *(const float4*)(Ab + (size_t)lrow * K + k0 + lseg);
        float4 w4 = *(const float4*)(Wb + (size_t)lrow * K + k0 + lseg);
        As[lseg + 0][lrow] = a4.x; As[lseg + 1][lrow] = a4.y;
        As[lseg + 2][lrow] = a4.z; As[lseg + 3][lrow] = a4.w;
        Ws[lseg + 0][lrow] = w4.x; Ws[lseg + 1][lrow] = w4.y;
        Ws[lseg + 2][lrow] = w4.z; Ws[lseg + 3][lrow] = w4.w;
        __syncthreads();
        #pragma unroll
        for (int k = 0; k < 8; k++) {
            float4 a0 = *(const float4*)&As[k][ty * 8];
            float4 a1 = *(const float4*)&As[k][ty * 8 + 4];
            float4 b0 = *(const float4*)&Ws[k][tx * 8];
            float4 b1 = *(const float4*)&Ws[k][tx * 8 + 4];
            float av[8] = {a0.x, a0.y, a0.z, a0.w, a1.x, a1.y, a1.z, a1.w};
            float bv[8] = {b0.x, b0.y, b0.z, b0.w, b1.x, b1.y, b1.z, b1.w};
            #pragma unroll
            for (int i = 0; i < 8; i++)
                #pragma unroll
                for (int j = 0; j < 8; j++)
                    acc[i][j] += av[i] * bv[j];
        }
        __syncthreads();
    }

    const int colbase = blockIdx.x * 128 + tx * 8;
    float4 bz0 = make_float4(0, 0, 0, 0), bz1 = bz0;
    if (flags & FLAG_BIAS) {
        bz0 = *(const float4*)(bias + colbase);
        bz1 = *(const float4*)(bias + colbase + 4);
    }
    #pragma unroll
    for (int i = 0; i < 8; i++) {
        size_t row = (size_t)blockIdx.y * 128 + ty * 8 + i;
        float* crow = C + row * N + colbase;
        float4 v0 = make_float4(acc[i][0] + bz0.x, acc[i][1] + bz0.y,
                                acc[i][2] + bz0.z, acc[i][3] + bz0.w);
        float4 v1 = make_float4(acc[i][4] + bz1.x, acc[i][5] + bz1.y,
                                acc[i][6] + bz1.z, acc[i][7] + bz1.w);
        if (flags & FLAG_RES) {
            const float* rrow = R + row * N + colbase;
            float4 r0 = *(const float4*)rrow;
            float4 r1 = *(const float4*)(rrow + 4);
            v0.x += r0.x; v0.y += r0.y; v0.z += r0.z; v0.w += r0.w;
            v1.x += r1.x; v1.y += r1.y; v1.z += r1.z; v1.w += r1.w;
        }
        if (flags & FLAG_GELU) {
            v0.x = gelu_exact(v0.x); v0.y = gelu_exact(v0.y);
            v0.z = gelu_exact(v0.z); v0.w = gelu_exact(v0.w);
            v1.x = gelu_exact(v1.x); v1.y = gelu_exact(v1.y);
            v1.z = gelu_exact(v1.z); v1.w = gelu_exact(v1.w);
        }
        *(float4*)crow       = v0;
        *(float4*)(crow + 4) = v1;
    }
}

// ------------------------- embedding: circular conv(C=2,k=3) + PE -----------
// PE: arguments computed in fp32 exactly as XLA does; exp/sin/cos evaluated
// in double on those fp32 arguments => matches accurate-f32 libm to ~1 ulp,
// independent of --use_fast_math.
__global__ void embed_kernel(const float* __restrict__ xe,
                             const float* __restrict__ w,
                             float* __restrict__ X)
{
    int i = blockIdx.x * blockDim.x + threadIdx.x;
    if (i >= BATCH * LMAX * D_MODEL) return;
    int d = i & 511;
    int l = (i >> 9) & (LMAX - 1);
    int b = i >> 20;
    float acc = 0.f;
    #pragma unroll
    for (int j = 0; j < 3; j++) {
        int ls = l + j - 1;
        if (ls < 0) ls += LMAX; else if (ls >= LMAX) ls -= LMAX;
        const float* xr = xe + ((size_t)b * LMAX + ls) * 2;
        acc += xr[0] * w[d * 6 + j] + xr[1] * w[d * 6 + 3 + j];
    }
    int kk = d >> 1;
    // f32 constant = f32(-log(10000)/512); product in fp32 (as XLA does)
    float prod = (float)(2 * kk) * -0.017988946039015984f;
    float divf = (float)exp((double)prod);      // accurate f32 exp
    float angf = (float)l * divf;               // fp32 multiply (as XLA)
    float pe   = (d & 1) ? (float)cos((double)angf)
                         : (float)sin((double)angf);
    X[i] = acc + pe;
}

// ------------------------- M = max_j(Q.K_idx) - sum_j(Q.K_idx)/L -------------
__global__ void msample_kernel(const float* __restrict__ Q,
                               const float* __restrict__ K,
                               const int* __restrict__ idx,
                               float* __restrict__ M, int L, int U)
{
    int w    = (blockIdx.x * blockDim.x + threadIdx.x) >> 5;
    int lane = threadIdx.x & 31;
    int total = BATCH * NH * L;
    if (w >= total) return;
    int l = w % L;
    int h = (w / L) % NH;
    int b = w / (L * NH);
    const float* qp = Q + ((size_t)b * L + l) * D_MODEL + h * DH;
    float q0 = qp[lane], q1 = qp[lane + 32];
    float mx = -3.4e38f, sm = 0.f;
    for (int j = 0; j < U; j++) {
        int ki = idx[l * U + j];
        const float* kp = K + ((size_t)b * L + ki) * D_MODEL + h * DH;
        float p = q0 * kp[lane] + q1 * kp[lane + 32];
        #pragma unroll
        for (int o = 16; o > 0; o >>= 1) p += __shfl_xor_sync(0xffffffffu, p, o);
        mx = fmaxf(mx, p);
        sm += p;
    }
    if (lane == 0) M[((size_t)b * NH + h) * L + l] = mx - sm / (float)L;
}

// ------------------------- top-u selection (set semantics) ------------------
__global__ void topk_kernel(const float* __restrict__ M, int* __restrict__ top,
                            int L, int U)
{
    __shared__ float vals[LMAX];
    __shared__ unsigned char flags[LMAX];
    __shared__ float rv[256];
    __shared__ int   ri[256];
    int row = blockIdx.x;
    int t   = threadIdx.x;
    const float* mrow = M + (size_t)row * L;
    for (int l = t; l < L; l += 256) { vals[l] = mrow[l]; flags[l] = 0; }
    __syncthreads();
    for (int pass = 0; pass < U; pass++) {
        float bv = -3.4e38f; int bi = 0x7fffffff;
        for (int l = t; l < L; l += 256) {
            if (!flags[l]) {
                float v = vals[l];
                if (v > bv || (v == bv && l < bi)) { bv = v; bi = l; }
            }
        }
        rv[t] = bv; ri[t] = bi;
        __syncthreads();
        for (int s = 128; s > 0; s >>= 1) {
            if (t < s) {
                float ov = rv[t + s]; int oi = ri[t + s];
                if (ov > rv[t] || (ov == rv[t] && oi < ri[t])) { rv[t] = ov; ri[t] = oi; }
            }
            __syncthreads();
        }
        if (t == 0) { top[row * UMAX + pass] = ri[0]; flags[ri[0]] = 1; }
        __syncthreads();
    }
}

// ------------------------- V mean over L ------------------------------------
__global__ void vmean_kernel(const float* __restrict__ V, float* __restrict__ vm,
                             int L)
{
    __shared__ float red[256];
    int row = blockIdx.x;              // b*NH + h
    int b = row / NH, h = row % NH;
    int t = threadIdx.x;
    int e = t & 63, grp = t >> 6;
    float acc = 0.f;
    for (int l = grp; l < L; l += 4)
        acc += V[((size_t)b * L + l) * D_MODEL + h * DH + e];
    red[t] = acc;
    __syncthreads();
    if (t < 64)
        vm[(size_t)row * DH + t] =
            (red[t] + red[t + 64] + red[t + 128] + red[t + 192]) / (float)L;
}

// ------------------------- fill O with broadcast V-mean ---------------------
__global__ void ofill_kernel(const float* __restrict__ vm, float* __restrict__ O,
                             int n, int L)
{
    int i = blockIdx.x * blockDim.x + threadIdx.x;
    if (i >= n) return;
    int d = i & 511;
    int b = i / (L * 512);
    O[i] = vm[(b * NH + (d >> 6)) * 64 + (d & 63)];
}

// ------------------------- full attention for selected queries --------------
__global__ void attn_kernel(const float* __restrict__ Q, const float* __restrict__ K,
                            const float* __restrict__ V, const int* __restrict__ top,
                            float* __restrict__ O, int L, int U)
{
    __shared__ float q[DH];
    __shared__ float sc[LMAX];
    __shared__ float red[256];
    int j   = blockIdx.x % U;
    int row = blockIdx.x / U;          // b*NH + h
    int b = row / NH, h = row % NH;
    int t = threadIdx.x;
    int lane = t & 31, w = t >> 5;
    int qi = top[row * UMAX + j];
    if (t < DH) q[t] = Q[((size_t)b * L + qi) * D_MODEL + h * DH + t];
    __syncthreads();
    for (int l = w; l < L; l += 8) {
        const float* kp = K + ((size_t)b * L + l) * D_MODEL + h * DH;
        float p = q[lane] * kp[lane] + q[lane + 32] * kp[lane + 32];
        #pragma unroll
        for (int o = 16; o > 0; o >>= 1) p += __shfl_xor_sync(0xffffffffu, p, o);
        if (lane == 0) sc[l] = p * 0.125f;
    }
    __syncthreads();
    float mx = -3.4e38f;
    for (int l = t; l < L; l += 256) mx = fmaxf(mx, sc[l]);
    red[t] = mx; __syncthreads();
    for (int s = 128; s > 0; s >>= 1) {
        if (t < s) red[t] = fmaxf(red[t], red[t + s]);
        __syncthreads();
    }
    mx = red[0]; __syncthreads();
    float sm = 0.f;
    for (int l = t; l < L; l += 256) {
        float e_ = expf(sc[l] - mx);
        sc[l] = e_;
        sm += e_;
    }
    red[t] = sm; __syncthreads();
    for (int s = 128; s > 0; s >>= 1) {
        if (t < s) red[t] += red[t + s];
        __syncthreads();
    }
    float inv = 1.f / red[0];
    __syncthreads();
    int e = t & 63, grp = t >> 6;
    float acc = 0.f;
    for (int l = grp; l < L; l += 4)
        acc += (sc[l] * inv) * V[((size_t)b * L + l) * D_MODEL + h * DH + e];
    red[t] = acc;
    __syncthreads();
    if (t < 64)
        O[((size_t)b * L + qi) * D_MODEL + h * DH + t] =
            red[t] + red[t + 64] + red[t + 128] + red[t + 192];
}

// ------------------------- LayerNorm (two-pass variance, D=512) -------------
__global__ void ln_kernel(const float* __restrict__ X, const float* __restrict__ g,
                          const float* __restrict__ b, float* __restrict__ Y)
{
    __shared__ float s1[4], s2[4];
    int row = blockIdx.x, t = threadIdx.x;
    const float4 v = ((const float4*)(X + (size_t)row * D_MODEL))[t];
    float s = v.x + v.y + v.z + v.w;
    #pragma unroll
    for (int o = 16; o > 0; o >>= 1) s += __shfl_xor_sync(0xffffffffu, s, o);
    if ((t & 31) == 0) s1[t >> 5] = s;
    __syncthreads();
    float mean = (s1[0] + s1[1] + s1[2] + s1[3]) * (1.f / 512.f);
    float dx = v.x - mean, dy = v.y - mean, dz = v.z - mean, dw = v.w - mean;
    float ss = dx * dx + dy * dy + dz * dz + dw * dw;
    #pragma unroll
    for (int o = 16; o > 0; o >>= 1) ss += __shfl_xor_sync(0xffffffffu, ss, o);
    if ((t & 31) == 0) s2[t >> 5] = ss;
    __syncthreads();
    float var = (s2[0] + s2[1] + s2[2] + s2[3]) * (1.f / 512.f);
    float inv = 1.f / sqrtf(var + 1e-5f);
    const float4 g4 = ((const float4*)g)[t];
    const float4 b4 = ((const float4*)b)[t];
    float4 o;
    o.x = dx * inv * g4.x + b4.x;
    o.y = dy * inv * g4.y + b4.y;
    o.z = dz * inv * g4.z + b4.z;
    o.w = dw * inv * g4.w + b4.w;
    ((float4*)(Y + (size_t)row * D_MODEL))[t] = o;
}

// ------------------------- conv-distill helpers -----------------------------
// weight relayout: WC[n][j*512+c] = cv_w[n][c][j]
__global__ void wtrans_kernel(const float* __restrict__ cv, float* __restrict__ WC)
{
    int i = blockIdx.x * blockDim.x + threadIdx.x;
    if (i >= D_MODEL * 3 * D_MODEL) return;
    int n = i / 1536, k = i % 1536;
    int j = k / 512, c = k % 512;
    WC[i] = cv[(size_t)n * 1536 + c * 3 + j];
}

// XCAT[(b,l)][j*512+c] = X[b, (l+j-1) mod L, c]
__global__ void xcat_kernel(const float* __restrict__ X, float* __restrict__ XC,
                            int L)
{
    int m = blockIdx.x;                // b*L + l
    int t = threadIdx.x;               // 128
    int b = m / L, l = m % L;
    float4* dst = (float4*)(XC + (size_t)m * 1536);
    #pragma unroll
    for (int r = 0; r < 3; r++) {
        int ls = l + r - 1;
        if (ls < 0) ls += L; else if (ls >= L) ls -= L;
        dst[r * 128 + t] = ((const float4*)(X + ((size_t)b * L + ls) * 512))[t];
    }
}

__global__ void scale_elu_kernel(float* __restrict__ Y, const float* __restrict__ bg,
                                 const float* __restrict__ bb, int n)
{
    int i = blockIdx.x * blockDim.x + threadIdx.x;
    if (i >= n) return;
    int d = i & 511;
    float v = Y[i] * 0.9999950000374997f * bg[d] + bb[d];   // / sqrt(1+1e-5)
    Y[i] = v > 0.f ? v : expm1f(v);
}

// maxpool k=3 s=2 pad=1(-inf): out[m] = max(y[2m-1],y[2m],y[2m+1])
__global__ void pool_kernel(const float* __restrict__ Y, float* __restrict__ X,
                            int L)
{
    int Lh = L >> 1;
    int i = blockIdx.x * blockDim.x + threadIdx.x;
    if (i >= BATCH * Lh * 512) return;
    int d = i & 511;
    int m = (i >> 9) % Lh;
    int b = i / (Lh * 512);
    const float* yb = Y + (size_t)b * L * 512 + d;
    float v = fmaxf(yb[(size_t)(2 * m) * 512], yb[(size_t)(2 * m + 1) * 512]);
    if (m > 0) v = fmaxf(v, yb[(size_t)(2 * m - 1) * 512]);
    X[i] = v;
}

// ---------------------------------------------------------------------------
extern "C" void kernel_launch(void* const* d_in, const int* in_sizes, int n_in,
                              void* d_out, int out_size)
{
    (void)in_sizes; (void)n_in; (void)out_size;
    const float* x_enc = (const float*)d_in[0];
    const float* emb_w = (const float*)d_in[1];
    const float* Wq  = (const float*)d_in[2];
    const float* bq  = (const float*)d_in[3];
    const float* Wk  = (const float*)d_in[4];
    const float* bk  = (const float*)d_in[5];
    const float* Wv  = (const float*)d_in[6];
    const float* bv  = (const float*)d_in[7];
    const float* Wo  = (const float*)d_in[8];
    const float* bo  = (const float*)d_in[9];
    const float* ln1g = (const float*)d_in[10];
    const float* ln1b = (const float*)d_in[11];
    const float* W1  = (const float*)d_in[12];
    const float* b1  = (const float*)d_in[13];
    const float* W2  = (const float*)d_in[14];
    const float* b2  = (const float*)d_in[15];
    const float* ln2g = (const float*)d_in[16];
    const float* ln2b = (const float*)d_in[17];
    const float* cvw = (const float*)d_in[18];
    const float* cvb = (const float*)d_in[19];
    const float* bng = (const float*)d_in[20];
    const float* bnb = (const float*)d_in[21];
    const float* ngp = (const float*)d_in[22];
    const float* nbp = (const float*)d_in[23];

    float *X, *XN, *Yb, *Qb, *Kb, *Vb, *Ob, *H1b, *XC, *CVb, *WCb, *Mb, *VMb;
    int *IDXb, *TOPb;
    cudaGetSymbolAddress((void**)&X,   g_X);
    cudaGetSymbolAddress((void**)&XN,  g_XN);
    cudaGetSymbolAddress((void**)&Yb,  g_Y);
    cudaGetSymbolAddress((void**)&Qb,  g_Q);
    cudaGetSymbolAddress((void**)&Kb,  g_K);
    cudaGetSymbolAddress((void**)&Vb,  g_V);
    cudaGetSymbolAddress((void**)&Ob,  g_O);
    cudaGetSymbolAddress((void**)&H1b, g_H1);
    cudaGetSymbolAddress((void**)&XC,  g_XC);
    cudaGetSymbolAddress((void**)&CVb, g_CV);
    cudaGetSymbolAddress((void**)&WCb, g_WC);
    cudaGetSymbolAddress((void**)&Mb,  g_M);
    cudaGetSymbolAddress((void**)&VMb, g_VM);
    cudaGetSymbolAddress((void**)&IDXb, g_IDX);
    cudaGetSymbolAddress((void**)&TOPb, g_TOP);

    // embedding
    {
        int total = BATCH * LMAX * D_MODEL;
        embed_kernel<<<(total + 255) / 256, 256>>>(x_enc, emb_w, X);
    }

    int L = LMAX;
    for (int layer = 0; layer < 3; layer++) {
        int U = 5 * (int)ceil(log((double)L));   // 40, 35, 35
        if (U > L) U = L;
        int Mrows = BATCH * L;
        dim3 gg(D_MODEL / 128, Mrows / 128);

        const float* wq = Wq + (size_t)layer * 512 * 512;
        const float* wk = Wk + (size_t)layer * 512 * 512;
        const float* wv = Wv + (size_t)layer * 512 * 512;
        const float* wo = Wo + (size_t)layer * 512 * 512;
        const float* w1 = W1 + (size_t)layer * 512 * 512;
        const float* w2 = W2 + (size_t)layer * 512 * 512;

        // QKV projections
        sgemm_kernel<<<gg, 256>>>(X, wq, bq + layer * 512, nullptr, Qb, 512, 512, FLAG_BIAS);
        sgemm_kernel<<<gg, 256>>>(X, wk, bk + layer * 512, nullptr, Kb, 512, 512, FLAG_BIAS);
        sgemm_kernel<<<gg, 256>>>(X, wv, bv + layer * 512, nullptr, Vb, 512, 512, FLAG_BIAS);

        // JAX PRNG, partitionable semantics:
        //   rng = fold_in(key(42), layer)            (not config-gated)
        //   k1,k2 = split(rng)  [foldlike: key_i = threefry(rng, (0, i))]
        //   idx = random_bits(k2) & (L-1)            (span L = power of two)
        uint32_t f0, f1, k2a, k2b;
        threefry2x32(0u, 42u, 0u, (uint32_t)layer, &f0, &f1);
        threefry2x32(f0, f1, 0u, 1u, &k2a, &k2b);
        int nidx = L * U;
        idx_kernel<<<(nidx + 255) / 256, 256>>>(k2a, k2b, nidx, (unsigned)(L - 1), IDXb);

        // sparsity measure, top-u, V-mean, broadcast, attention
        int warps = BATCH * NH * L;
        msample_kernel<<<(warps * 32 + 255) / 256, 256>>>(Qb, Kb, IDXb, Mb, L, U);
        topk_kernel<<<BATCH * NH, 256>>>(Mb, TOPb, L, U);
        vmean_kernel<<<BATCH * NH, 256>>>(Vb, VMb, L);
        ofill_kernel<<<(Mrows * 512 + 255) / 256, 256>>>(VMb, Ob, Mrows * 512, L);
        attn_kernel<<<BATCH * NH * U, 256>>>(Qb, Kb, Vb, TOPb, Ob, L, U);

        // out-proj + residual, LN1, FFN(GELU), residual, LN2
        sgemm_kernel<<<gg, 256>>>(Ob, wo, bo + layer * 512, X, Yb, 512, 512, FLAG_BIAS | FLAG_RES);
        ln_kernel<<<Mrows, 128>>>(Yb, ln1g + layer * 512, ln1b + layer * 512, XN);
        sgemm_kernel<<<gg, 256>>>(XN, w1, b1 + layer * 512, nullptr, H1b, 512, 512, FLAG_BIAS | FLAG_GELU);
        sgemm_kernel<<<gg, 256>>>(H1b, w2, b2 + layer * 512, XN, Yb, 512, 512, FLAG_BIAS | FLAG_RES);
        ln_kernel<<<Mrows, 128>>>(Yb, ln2g + layer * 512, ln2b + layer * 512, X);

        // conv distill
        if (layer < 2) {
            wtrans_kernel<<<(512 * 1536 + 255) / 256, 256>>>(cvw + (size_t)layer * 512 * 1536, WCb);
            xcat_kernel<<<Mrows, 128>>>(X, XC, L);
            sgemm_kernel<<<gg, 256>>>(XC, WCb, cvb + layer * 512, nullptr, CVb, 512, 1536, FLAG_BIAS);
            scale_elu_kernel<<<(Mrows * 512 + 255) / 256, 256>>>(CVb, bng + layer * 512, bnb + layer * 512, Mrows * 512);
            int Lh = L / 2;
            pool_kernel<<<(BATCH * Lh * 512 + 255) / 256, 256>>>(CVb, X, L);
            L = Lh;
        }
    }

    // final layer norm -> output (4, 512, 512)
    ln_kernel<<<BATCH * L, 128>>>(X, ngp, nbp, (float*)d_out);
}

// round 6
// speedup vs baseline: 1.4038x; 1.4038x over previous
#include <cuda_runtime.h>
#include <stdint.h>
#include <math.h>

// ---------------------------------------------------------------------------
// InformerEncoder: B=4, L0=2048, C=2, D=512, F=512, H=8, dh=64, EL=3
// Exact fp32 everywhere; PE via double transcendentals on fp32 args;
// jax_threefry_partitionable PRNG. (R4 PASSED with this numerics model.)
// ---------------------------------------------------------------------------
#define D_MODEL 512
#define BATCH   4
#define LMAX    2048
#define NH      8
#define DH      64
#define UMAX    40
#define NROW    (BATCH*NH)      // 32
#define APAD    65              // padded row stride in attn smem

#define FLAG_BIAS 1
#define FLAG_RES  2
#define FLAG_GELU 4
#define FLAG_ELU  8

// ------------------------- scratch (static device globals) ------------------
__device__ float g_X   [BATCH*LMAX*D_MODEL];
__device__ float g_XN  [BATCH*LMAX*D_MODEL];
__device__ float g_Y   [BATCH*LMAX*D_MODEL];
__device__ float g_Q   [BATCH*LMAX*D_MODEL];
__device__ float g_K   [BATCH*LMAX*D_MODEL];
__device__ float g_V   [BATCH*LMAX*D_MODEL];
__device__ float g_O   [BATCH*LMAX*D_MODEL];
__device__ float g_H1  [BATCH*LMAX*D_MODEL];
__device__ float g_XC  [BATCH*LMAX*3*D_MODEL];
__device__ float g_CV  [BATCH*LMAX*D_MODEL];
__device__ float g_WC  [D_MODEL*3*D_MODEL];
__device__ float g_PE  [LMAX*D_MODEL];
__device__ int   g_IDX [LMAX*UMAX];
__device__ float g_M   [NROW*LMAX];
__device__ int   g_TOP [NROW*UMAX];
__device__ float g_VM  [NROW*DH];
__device__ float g_PM  [4*NROW*UMAX];
__device__ float g_PS  [4*NROW*UMAX];
__device__ float g_PA  [4*NROW*UMAX*DH];

// ------------------------- threefry2x32 (JAX-compatible) --------------------
__host__ __device__ inline void threefry2x32(uint32_t k0, uint32_t k1,
                                             uint32_t x0, uint32_t x1,
                                             uint32_t* o0, uint32_t* o1)
{
    uint32_t ks0 = k0, ks1 = k1, ks2 = k0 ^ k1 ^ 0x1BD11BDAu;
    uint32_t ks[3] = {ks0, ks1, ks2};
    x0 += ks0; x1 += ks1;
    const int rA[4] = {13, 15, 26, 6};
    const int rB[4] = {17, 29, 16, 24};
    #pragma unroll
    for (int g = 0; g < 5; ++g) {
        const int* r = (g & 1) ? rB : rA;
        #pragma unroll
        for (int i = 0; i < 4; ++i) {
            x0 += x1;
            x1 = (x1 << r[i]) | (x1 >> (32 - r[i]));
            x1 ^= x0;
        }
        x0 += ks[(g + 1) % 3];
        x1 += ks[(g + 2) % 3] + (uint32_t)(g + 1);
    }
    *o0 = x0; *o1 = x1;
}

// partitionable random_bits: counter (0, j); draw = out0 ^ out1
__global__ void idx_kernel(uint32_t k0, uint32_t k1, int n, unsigned mask,
                           int* __restrict__ idx)
{
    int j = blockIdx.x * blockDim.x + threadIdx.x;
    if (j >= n) return;
    uint32_t o0, o1;
    threefry2x32(k0, k1, 0u, (uint32_t)j, &o0, &o1);
    idx[j] = (int)((o0 ^ o1) & mask);
}

// ------------------------- SGEMM v2: double-buffered, BK=16 -----------------
__device__ __forceinline__ float gelu_exact(float x)
{
    return 0.5f * x * (1.0f + erff(x * 0.70710678118654752f));
}

__device__ __forceinline__ void gemm_tile(
    const float* __restrict__ A, const float* __restrict__ W,
    const float* __restrict__ bias, const float* __restrict__ R,
    const float* __restrict__ eg, const float* __restrict__ eb,
    float* __restrict__ C, int N, int K, int flags, int bx, int by)
{
    __shared__ float As[2][16][128];
    __shared__ float Ws[2][16][128];
    const int t    = threadIdx.x;
    const int tx   = t & 15;
    const int ty   = t >> 4;
    const int lrow = t >> 1;
    const int lk   = (t & 1) << 3;

    const float* Ab = A + (size_t)by * 128 * K + (size_t)lrow * K + lk;
    const float* Wb = W + (size_t)bx * 128 * K + (size_t)lrow * K + lk;

    float acc[8][8];
    #pragma unroll
    for (int i = 0; i < 8; i++)
        #pragma unroll
        for (int j = 0; j < 8; j++) acc[i][j] = 0.f;

    float4 pa0 = *(const float4*)(Ab + 0);
    float4 pa1 = *(const float4*)(Ab + 4);
    float4 pw0 = *(const float4*)(Wb + 0);
    float4 pw1 = *(const float4*)(Wb + 4);
    {
        float* as = &As[0][lk][lrow];
        as[0*128]=pa0.x; as[1*128]=pa0.y; as[2*128]=pa0.z; as[3*128]=pa0.w;
        as[4*128]=pa1.x; as[5*128]=pa1.y; as[6*128]=pa1.z; as[7*128]=pa1.w;
        float* ws = &Ws[0][lk][lrow];
        ws[0*128]=pw0.x; ws[1*128]=pw0.y; ws[2*128]=pw0.z; ws[3*128]=pw0.w;
        ws[4*128]=pw1.x; ws[5*128]=pw1.y; ws[6*128]=pw1.z; ws[7*128]=pw1.w;
    }
    __syncthreads();

    const int nb = K >> 4;
    for (int kb = 0; kb < nb; kb++) {
        const int cur = kb & 1;
        if (kb + 1 < nb) {
            const float* An = Ab + (size_t)(kb + 1) * 16;
            const float* Wn = Wb + (size_t)(kb + 1) * 16;
            pa0 = *(const float4*)(An + 0);
            pa1 = *(const float4*)(An + 4);
            pw0 = *(const float4*)(Wn + 0);
            pw1 = *(const float4*)(Wn + 4);
        }
        #pragma unroll
        for (int k = 0; k < 16; k++) {
            float4 a0 = *(const float4*)&As[cur][k][ty * 8];
            float4 a1 = *(const float4*)&As[cur][k][ty * 8 + 4];
            float4 b0 = *(const float4*)&Ws[cur][k][tx * 8];
            float4 b1 = *(const float4*)&Ws[cur][k][tx * 8 + 4];
            float av[8] = {a0.x, a0.y, a0.z, a0.w, a1.x, a1.y, a1.z, a1.w};
            float bv[8] = {b0.x, b0.y, b0.z, b0.w, b1.x, b1.y, b1.z, b1.w};
            #pragma unroll
            for (int i = 0; i < 8; i++)
                #pragma unroll
                for (int j = 0; j < 8; j++)
                    acc[i][j] += av[i] * bv[j];
        }
        if (kb + 1 < nb) {
            const int nxt = cur ^ 1;
            float* as = &As[nxt][lk][lrow];
            as[0*128]=pa0.x; as[1*128]=pa0.y; as[2*128]=pa0.z; as[3*128]=pa0.w;
            as[4*128]=pa1.x; as[5*128]=pa1.y; as[6*128]=pa1.z; as[7*128]=pa1.w;
            float* ws = &Ws[nxt][lk][lrow];
            ws[0*128]=pw0.x; ws[1*128]=pw0.y; ws[2*128]=pw0.z; ws[3*128]=pw0.w;
            ws[4*128]=pw1.x; ws[5*128]=pw1.y; ws[6*128]=pw1.z; ws[7*128]=pw1.w;
        }
        __syncthreads();
    }

    const int colbase = bx * 128 + tx * 8;
    float4 bz0 = make_float4(0, 0, 0, 0), bz1 = bz0;
    if (flags & FLAG_BIAS) {
        bz0 = *(const float4*)(bias + colbase);
        bz1 = *(const float4*)(bias + colbase + 4);
    }
    float4 g0, g1, e0, e1;
    if (flags & FLAG_ELU) {
        g0 = *(const float4*)(eg + colbase);
        g1 = *(const float4*)(eg + colbase + 4);
        e0 = *(const float4*)(eb + colbase);
        e1 = *(const float4*)(eb + colbase + 4);
    }
    #pragma unroll
    for (int i = 0; i < 8; i++) {
        size_t row = (size_t)by * 128 + ty * 8 + i;
        float* crow = C + row * N + colbase;
        float4 v0 = make_float4(acc[i][0] + bz0.x, acc[i][1] + bz0.y,
                                acc[i][2] + bz0.z, acc[i][3] + bz0.w);
        float4 v1 = make_float4(acc[i][4] + bz1.x, acc[i][5] + bz1.y,
                                acc[i][6] + bz1.z, acc[i][7] + bz1.w);
        if (flags & FLAG_RES) {
            const float* rrow = R + row * N + colbase;
            float4 r0 = *(const float4*)rrow;
            float4 r1 = *(const float4*)(rrow + 4);
            v0.x += r0.x; v0.y += r0.y; v0.z += r0.z; v0.w += r0.w;
            v1.x += r1.x; v1.y += r1.y; v1.z += r1.z; v1.w += r1.w;
        }
        if (flags & FLAG_GELU) {
            v0.x = gelu_exact(v0.x); v0.y = gelu_exact(v0.y);
            v0.z = gelu_exact(v0.z); v0.w = gelu_exact(v0.w);
            v1.x = gelu_exact(v1.x); v1.y = gelu_exact(v1.y);
            v1.z = gelu_exact(v1.z); v1.w = gelu_exact(v1.w);
        }
        if (flags & FLAG_ELU) {
            const float cst = 0.9999950000374997f;   // 1/sqrt(1+1e-5)
            v0.x = v0.x*cst*g0.x + e0.x; v0.y = v0.y*cst*g0.y + e0.y;
            v0.z = v0.z*cst*g0.z + e0.z; v0.w = v0.w*cst*g0.w + e0.w;
            v1.x = v1.x*cst*g1.x + e1.x; v1.y = v1.y*cst*g1.y + e1.y;
            v1.z = v1.z*cst*g1.z + e1.z; v1.w = v1.w*cst*g1.w + e1.w;
            v0.x = v0.x > 0.f ? v0.x : expm1f(v0.x);
            v0.y = v0.y > 0.f ? v0.y : expm1f(v0.y);
            v0.z = v0.z > 0.f ? v0.z : expm1f(v0.z);
            v0.w = v0.w > 0.f ? v0.w : expm1f(v0.w);
            v1.x = v1.x > 0.f ? v1.x : expm1f(v1.x);
            v1.y = v1.y > 0.f ? v1.y : expm1f(v1.y);
            v1.z = v1.z > 0.f ? v1.z : expm1f(v1.z);
            v1.w = v1.w > 0.f ? v1.w : expm1f(v1.w);
        }
        *(float4*)crow       = v0;
        *(float4*)(crow + 4) = v1;
    }
}

__global__ __launch_bounds__(256, 2)
void sgemm_kernel(const float* __restrict__ A, const float* __restrict__ W,
                  const float* __restrict__ bias, const float* __restrict__ R,
                  const float* __restrict__ eg, const float* __restrict__ eb,
                  float* __restrict__ C, int N, int K, int flags)
{
    gemm_tile(A, W, bias, R, eg, eb, C, N, K, flags, blockIdx.x, blockIdx.y);
}

__global__ __launch_bounds__(256, 2)
void qkv_kernel(const float* __restrict__ A,
                const float* __restrict__ wq, const float* __restrict__ wk,
                const float* __restrict__ wv,
                const float* __restrict__ bq, const float* __restrict__ bk,
                const float* __restrict__ bv,
                float* __restrict__ Qo, float* __restrict__ Ko,
                float* __restrict__ Vo, int K)
{
    int which = blockIdx.z;
    const float* W = which == 0 ? wq : (which == 1 ? wk : wv);
    const float* B = which == 0 ? bq : (which == 1 ? bk : bv);
    float*       C = which == 0 ? Qo : (which == 1 ? Ko : Vo);
    gemm_tile(A, W, B, nullptr, nullptr, nullptr, C, 512, K, FLAG_BIAS,
              blockIdx.x, blockIdx.y);
}

// ------------------------- PE table + embedding -----------------------------
__global__ void pe_kernel(float* __restrict__ PE)
{
    int i = blockIdx.x * blockDim.x + threadIdx.x;
    if (i >= LMAX * D_MODEL) return;
    int d = i & 511;
    int l = i >> 9;
    int kk = d >> 1;
    float prod = (float)(2 * kk) * -0.017988946039015984f;
    float divf = (float)exp((double)prod);
    float angf = (float)l * divf;
    PE[i] = (d & 1) ? (float)cos((double)angf) : (float)sin((double)angf);
}

__global__ void embed_kernel(const float* __restrict__ xe,
                             const float* __restrict__ w,
                             const float* __restrict__ PE,
                             float* __restrict__ X)
{
    int i = blockIdx.x * blockDim.x + threadIdx.x;
    if (i >= BATCH * LMAX * D_MODEL) return;
    int d = i & 511;
    int l = (i >> 9) & (LMAX - 1);
    int b = i >> 20;
    float acc = 0.f;
    #pragma unroll
    for (int j = 0; j < 3; j++) {
        int ls = l + j - 1;
        if (ls < 0) ls += LMAX; else if (ls >= LMAX) ls -= LMAX;
        const float* xr = xe + ((size_t)b * LMAX + ls) * 2;
        acc += xr[0] * w[d * 6 + j] + xr[1] * w[d * 6 + 3 + j];
    }
    X[i] = acc + PE[i & (LMAX * D_MODEL - 1)];
}

// ------------------------- M = max_j(Q.K_idx) - sum_j(Q.K_idx)/L -------------
__global__ void msample_kernel(const float* __restrict__ Q,
                               const float* __restrict__ K,
                               const int* __restrict__ idx,
                               float* __restrict__ M, int L, int U)
{
    int w    = (blockIdx.x * blockDim.x + threadIdx.x) >> 5;
    int lane = threadIdx.x & 31;
    int total = NROW * L;
    if (w >= total) return;
    int l = w % L;
    int h = (w / L) % NH;
    int b = w / (L * NH);
    const float* qp = Q + ((size_t)b * L + l) * D_MODEL + h * DH;
    float q0 = qp[lane], q1 = qp[lane + 32];
    float mx = -3.4e38f, sm = 0.f;
    #pragma unroll 4
    for (int j = 0; j < U; j++) {
        int ki = idx[l * U + j];
        const float* kp = K + ((size_t)b * L + ki) * D_MODEL + h * DH;
        float p = q0 * kp[lane] + q1 * kp[lane + 32];
        #pragma unroll
        for (int o = 16; o > 0; o >>= 1) p += __shfl_xor_sync(0xffffffffu, p, o);
        mx = fmaxf(mx, p);
        sm += p;
    }
    if (lane == 0) M[((size_t)b * NH + h) * L + l] = mx - sm / (float)L;
}

// ------------------------- top-u selection (set semantics) ------------------
__global__ void topk_kernel(const float* __restrict__ M, int* __restrict__ top,
                            int L, int U)
{
    __shared__ float vals[LMAX];
    __shared__ unsigned char flags[LMAX];
    __shared__ float rv[256];
    __shared__ int   ri[256];
    int row = blockIdx.x;
    int t   = threadIdx.x;
    const float* mrow = M + (size_t)row * L;
    for (int l = t; l < L; l += 256) { vals[l] = mrow[l]; flags[l] = 0; }
    __syncthreads();
    for (int pass = 0; pass < U; pass++) {
        float bv = -3.4e38f; int bi = 0x7fffffff;
        for (int l = t; l < L; l += 256) {
            if (!flags[l]) {
                float v = vals[l];
                if (v > bv || (v == bv && l < bi)) { bv = v; bi = l; }
            }
        }
        rv[t] = bv; ri[t] = bi;
        __syncthreads();
        for (int s = 128; s > 0; s >>= 1) {
            if (t < s) {
                float ov = rv[t + s]; int oi = ri[t + s];
                if (ov > rv[t] || (ov == rv[t] && oi < ri[t])) { rv[t] = ov; ri[t] = oi; }
            }
            __syncthreads();
        }
        if (t == 0) { top[row * UMAX + pass] = ri[0]; flags[ri[0]] = 1; }
        __syncthreads();
    }
}

// ------------------------- V mean over L ------------------------------------
__global__ void vmean_kernel(const float* __restrict__ V, float* __restrict__ vm,
                             int L)
{
    __shared__ float red[256];
    int row = blockIdx.x;
    int b = row / NH, h = row % NH;
    int t = threadIdx.x;
    int e = t & 63, grp = t >> 6;
    float acc = 0.f;
    for (int l = grp; l < L; l += 4)
        acc += V[((size_t)b * L + l) * D_MODEL + h * DH + e];
    red[t] = acc;
    __syncthreads();
    if (t < 64)
        vm[(size_t)row * DH + t] =
            (red[t] + red[t + 64] + red[t + 128] + red[t + 192]) / (float)L;
}

__global__ void ofill_kernel(const float* __restrict__ vm, float* __restrict__ O,
                             int n, int L)
{
    int i = blockIdx.x * blockDim.x + threadIdx.x;
    if (i >= n) return;
    int d = i & 511;
    int b = i / (L * 512);
    O[i] = vm[(b * NH + (d >> 6)) * 64 + (d & 63)];
}

// ------------------------- flash-style attention ----------------------------
// grid (nsplit, NROW); 256 thr; dyn smem: qs[UMAX][APAD], P[UMAX][APAD],
// Kt[64][APAD], Vt[64][APAD]. Each warp owns rows j = w + 8r (r<5).
__global__ void attn_kernel(const float* __restrict__ Q,
                            const float* __restrict__ K,
                            const float* __restrict__ V,
                            const int* __restrict__ top,
                            float* __restrict__ PM, float* __restrict__ PS,
                            float* __restrict__ PA,
                            int L, int U, int keys)
{
    extern __shared__ float smf[];
    float* qs = smf;                          // UMAX*APAD
    float* P  = qs + UMAX * APAD;             // UMAX*APAD (scores -> probs)
    float* Kt = P  + UMAX * APAD;             // 64*APAD
    float* Vt = Kt + 64 * APAD;               // 64*APAD
    __shared__ int qidx[UMAX];

    int split = blockIdx.x;
    int row   = blockIdx.y;                   // b*NH+h
    int b = row / NH, h = row % NH;
    int t = threadIdx.x, lane = t & 31, w = t >> 5;

    if (t < U) qidx[t] = top[row * UMAX + t];
    __syncthreads();
    for (int p = t; p < U * 64; p += 256) {
        int j = p >> 6, e = p & 63;
        qs[j * APAD + e] = Q[((size_t)(b * L + qidx[j])) * D_MODEL + h * DH + e];
    }

    float m0[5], s0[5], a0[5], a1[5];
    #pragma unroll
    for (int r = 0; r < 5; r++) { m0[r] = -3.4e38f; s0[r] = 0.f; a0[r] = 0.f; a1[r] = 0.f; }
    __syncthreads();

    int base0 = split * keys;
    int ntile = keys >> 6;
    for (int tl = 0; tl < ntile; tl++) {
        int kb = base0 + (tl << 6);
        for (int i = t; i < 1024; i += 256) {
            int r = i >> 4, c = (i & 15) << 2;
            size_t gi = ((size_t)(b * L + kb + r)) * D_MODEL + h * DH + c;
            float4 kv = *(const float4*)(K + gi);
            float* dk = &Kt[r * APAD + c];
            dk[0] = kv.x; dk[1] = kv.y; dk[2] = kv.z; dk[3] = kv.w;
            float4 vv = *(const float4*)(V + gi);
            float* dv = &Vt[r * APAD + c];
            dv[0] = vv.x; dv[1] = vv.y; dv[2] = vv.z; dv[3] = vv.w;
        }
        __syncthreads();

        // scores: thread covers rows {w+8r} x cols {lane, lane+32}
        {
            float d0[5], d1[5];
            #pragma unroll
            for (int r = 0; r < 5; r++) { d0[r] = 0.f; d1[r] = 0.f; }
            const float* k0 = &Kt[lane * APAD];
            const float* k1 = &Kt[(lane + 32) * APAD];
            #pragma unroll 8
            for (int e = 0; e < 64; e++) {
                float ke0 = k0[e], ke1 = k1[e];
                #pragma unroll
                for (int r = 0; r < 5; r++) {
                    float qe = qs[(w + (r << 3)) * APAD + e];
                    d0[r] += qe * ke0;
                    d1[r] += qe * ke1;
                }
            }
            #pragma unroll
            for (int r = 0; r < 5; r++) {
                int j = w + (r << 3);
                if (j < U) {
                    P[j * APAD + lane]      = d0[r] * 0.125f;
                    P[j * APAD + lane + 32] = d1[r] * 0.125f;
                }
            }
        }
        __syncwarp();

        // online softmax update per owned row; P <- probs (unnormalized)
        #pragma unroll
        for (int r = 0; r < 5; r++) {
            int j = w + (r << 3);
            if (j >= U) break;
            float v0 = P[j * APAD + lane], v1 = P[j * APAD + lane + 32];
            float tm = fmaxf(v0, v1);
            #pragma unroll
            for (int o = 16; o > 0; o >>= 1)
                tm = fmaxf(tm, __shfl_xor_sync(0xffffffffu, tm, o));
            float nm = fmaxf(m0[r], tm);
            float p0 = expf(v0 - nm), p1 = expf(v1 - nm);
            float ts = p0 + p1;
            #pragma unroll
            for (int o = 16; o > 0; o >>= 1)
                ts += __shfl_xor_sync(0xffffffffu, ts, o);
            float al = expf(m0[r] - nm);
            s0[r] = s0[r] * al + ts;
            a0[r] *= al; a1[r] *= al;
            m0[r] = nm;
            P[j * APAD + lane]      = p0;
            P[j * APAD + lane + 32] = p1;
        }
        __syncthreads();

        // acc += P @ Vt : same thread blocking (rows {w+8r}, dims {lane,lane+32})
        #pragma unroll 4
        for (int k = 0; k < 64; k++) {
            float ve0 = Vt[k * APAD + lane];
            float ve1 = Vt[k * APAD + lane + 32];
            #pragma unroll
            for (int r = 0; r < 5; r++) {
                float pk = P[(w + (r << 3)) * APAD + k];
                a0[r] += pk * ve0;
                a1[r] += pk * ve1;
            }
        }
        __syncthreads();
    }

    #pragma unroll
    for (int r = 0; r < 5; r++) {
        int j = w + (r << 3);
        if (j >= U) break;
        int pidx = (split * NROW + row) * UMAX + j;
        if (lane == 0) { PM[pidx] = m0[r]; PS[pidx] = s0[r]; }
        PA[(size_t)pidx * 64 + lane]      = a0[r];
        PA[(size_t)pidx * 64 + lane + 32] = a1[r];
    }
}

// combine split partials; one warp per (row, j)
__global__ void attn_merge(const float* __restrict__ PM,
                           const float* __restrict__ PS,
                           const float* __restrict__ PA,
                           const int* __restrict__ top,
                           float* __restrict__ O, int L, int U, int nsplit)
{
    int gw = (blockIdx.x * blockDim.x + threadIdx.x) >> 5;
    int lane = threadIdx.x & 31;
    if (gw >= NROW * U) return;
    int row = gw / U, j = gw % U;
    int b = row / NH, h = row % NH;
    float M = -3.4e38f;
    for (int i = 0; i < nsplit; i++)
        M = fmaxf(M, PM[(i * NROW + row) * UMAX + j]);
    float s = 0.f, acc0 = 0.f, acc1 = 0.f;
    for (int i = 0; i < nsplit; i++) {
        int pidx = (i * NROW + row) * UMAX + j;
        float sc = expf(PM[pidx] - M);
        s    += PS[pidx] * sc;
        acc0 += PA[(size_t)pidx * 64 + lane] * sc;
        acc1 += PA[(size_t)pidx * 64 + lane + 32] * sc;
    }
    float inv = 1.f / s;
    int qi = top[row * UMAX + j];
    size_t o = ((size_t)(b * L + qi)) * D_MODEL + h * DH;
    O[o + lane]      = acc0 * inv;
    O[o + lane + 32] = acc1 * inv;
}

// ------------------------- LayerNorm (two-pass variance) --------------------
__global__ void ln_kernel(const float* __restrict__ X, const float* __restrict__ g,
                          const float* __restrict__ b, float* __restrict__ Y)
{
    __shared__ float s1[4], s2[4];
    int row = blockIdx.x, t = threadIdx.x;
    const float4 v = ((const float4*)(X + (size_t)row * D_MODEL))[t];
    float s = v.x + v.y + v.z + v.w;
    #pragma unroll
    for (int o = 16; o > 0; o >>= 1) s += __shfl_xor_sync(0xffffffffu, s, o);
    if ((t & 31) == 0) s1[t >> 5] = s;
    __syncthreads();
    float mean = (s1[0] + s1[1] + s1[2] + s1[3]) * (1.f / 512.f);
    float dx = v.x - mean, dy = v.y - mean, dz = v.z - mean, dw = v.w - mean;
    float ss = dx * dx + dy * dy + dz * dz + dw * dw;
    #pragma unroll
    for (int o = 16; o > 0; o >>= 1) ss += __shfl_xor_sync(0xffffffffu, ss, o);
    if ((t & 31) == 0) s2[t >> 5] = ss;
    __syncthreads();
    float var = (s2[0] + s2[1] + s2[2] + s2[3]) * (1.f / 512.f);
    float inv = 1.f / sqrtf(var + 1e-5f);
    const float4 g4 = ((const float4*)g)[t];
    const float4 b4 = ((const float4*)b)[t];
    float4 o;
    o.x = dx * inv * g4.x + b4.x;
    o.y = dy * inv * g4.y + b4.y;
    o.z = dz * inv * g4.z + b4.z;
    o.w = dw * inv * g4.w + b4.w;
    ((float4*)(Y + (size_t)row * D_MODEL))[t] = o;
}

// ------------------------- conv-distill helpers -----------------------------
__global__ void wtrans_kernel(const float* __restrict__ cv, float* __restrict__ WC)
{
    int i = blockIdx.x * blockDim.x + threadIdx.x;
    if (i >= D_MODEL * 3 * D_MODEL) return;
    int n = i / 1536, k = i % 1536;
    int j = k / 512, c = k % 512;
    WC[i] = cv[(size_t)n * 1536 + c * 3 + j];
}

__global__ void xcat_kernel(const float* __restrict__ X, float* __restrict__ XC,
                            int L)
{
    int m = blockIdx.x;
    int t = threadIdx.x;
    int b = m / L, l = m % L;
    float4* dst = (float4*)(XC + (size_t)m * 1536);
    #pragma unroll
    for (int r = 0; r < 3; r++) {
        int ls = l + r - 1;
        if (ls < 0) ls += L; else if (ls >= L) ls -= L;
        dst[r * 128 + t] = ((const float4*)(X + ((size_t)b * L + ls) * 512))[t];
    }
}

__global__ void pool_kernel(const float* __restrict__ Y, float* __restrict__ X,
                            int L)
{
    int Lh = L >> 1;
    int i = blockIdx.x * blockDim.x + threadIdx.x;
    if (i >= BATCH * Lh * 512) return;
    int d = i & 511;
    int m = (i >> 9) % Lh;
    int b = i / (Lh * 512);
    const float* yb = Y + (size_t)b * L * 512 + d;
    float v = fmaxf(yb[(size_t)(2 * m) * 512], yb[(size_t)(2 * m + 1) * 512]);
    if (m > 0) v = fmaxf(v, yb[(size_t)(2 * m - 1) * 512]);
    X[i] = v;
}

// ---------------------------------------------------------------------------
extern "C" void kernel_launch(void* const* d_in, const int* in_sizes, int n_in,
                              void* d_out, int out_size)
{
    (void)in_sizes; (void)n_in; (void)out_size;
    const float* x_enc = (const float*)d_in[0];
    const float* emb_w = (const float*)d_in[1];
    const float* Wq  = (const float*)d_in[2];
    const float* bq  = (const float*)d_in[3];
    const float* Wk  = (const float*)d_in[4];
    const float* bk  = (const float*)d_in[5];
    const float* Wv  = (const float*)d_in[6];
    const float* bv  = (const float*)d_in[7];
    const float* Wo  = (const float*)d_in[8];
    const float* bo  = (const float*)d_in[9];
    const float* ln1g = (const float*)d_in[10];
    const float* ln1b = (const float*)d_in[11];
    const float* W1  = (const float*)d_in[12];
    const float* b1  = (const float*)d_in[13];
    const float* W2  = (const float*)d_in[14];
    const float* b2  = (const float*)d_in[15];
    const float* ln2g = (const float*)d_in[16];
    const float* ln2b = (const float*)d_in[17];
    const float* cvw = (const float*)d_in[18];
    const float* cvb = (const float*)d_in[19];
    const float* bng = (const float*)d_in[20];
    const float* bnb = (const float*)d_in[21];
    const float* ngp = (const float*)d_in[22];
    const float* nbp = (const float*)d_in[23];

    float *X, *XN, *Yb, *Qb, *Kb, *Vb, *Ob, *H1b, *XC, *CVb, *WCb, *Mb, *VMb;
    float *PEb, *PMb, *PSb, *PAb;
    int *IDXb, *TOPb;
    cudaGetSymbolAddress((void**)&X,   g_X);
    cudaGetSymbolAddress((void**)&XN,  g_XN);
    cudaGetSymbolAddress((void**)&Yb,  g_Y);
    cudaGetSymbolAddress((void**)&Qb,  g_Q);
    cudaGetSymbolAddress((void**)&Kb,  g_K);
    cudaGetSymbolAddress((void**)&Vb,  g_V);
    cudaGetSymbolAddress((void**)&Ob,  g_O);
    cudaGetSymbolAddress((void**)&H1b, g_H1);
    cudaGetSymbolAddress((void**)&XC,  g_XC);
    cudaGetSymbolAddress((void**)&CVb, g_CV);
    cudaGetSymbolAddress((void**)&WCb, g_WC);
    cudaGetSymbolAddress((void**)&PEb, g_PE);
    cudaGetSymbolAddress((void**)&Mb,  g_M);
    cudaGetSymbolAddress((void**)&VMb, g_VM);
    cudaGetSymbolAddress((void**)&PMb, g_PM);
    cudaGetSymbolAddress((void**)&PSb, g_PS);
    cudaGetSymbolAddress((void**)&PAb, g_PA);
    cudaGetSymbolAddress((void**)&IDXb, g_IDX);
    cudaGetSymbolAddress((void**)&TOPb, g_TOP);

    const int attn_smem = (UMAX * APAD * 2 + 64 * APAD * 2) * 4;   // 54080 B
    cudaFuncSetAttribute(attn_kernel,
                         cudaFuncAttributeMaxDynamicSharedMemorySize, attn_smem);

    // PE table + embedding
    pe_kernel<<<(LMAX * D_MODEL + 255) / 256, 256>>>(PEb);
    {
        int total = BATCH * LMAX * D_MODEL;
        embed_kernel<<<(total + 255) / 256, 256>>>(x_enc, emb_w, PEb, X);
    }

    int L = LMAX;
    for (int layer = 0; layer < 3; layer++) {
        int U = 5 * (int)ceil(log((double)L));   // 40, 35, 35
        if (U > L) U = L;
        int Mrows = BATCH * L;
        dim3 gg(D_MODEL / 128, Mrows / 128);

        const float* wq = Wq + (size_t)layer * 512 * 512;
        const float* wk = Wk + (size_t)layer * 512 * 512;
        const float* wv = Wv + (size_t)layer * 512 * 512;
        const float* wo = Wo + (size_t)layer * 512 * 512;
        const float* w1 = W1 + (size_t)layer * 512 * 512;
        const float* w2 = W2 + (size_t)layer * 512 * 512;

        // fused QKV projections (3 GEMMs in one launch)
        {
            dim3 gq(D_MODEL / 128, Mrows / 128, 3);
            qkv_kernel<<<gq, 256>>>(X, wq, wk, wv,
                                    bq + layer * 512, bk + layer * 512,
                                    bv + layer * 512, Qb, Kb, Vb, 512);
        }

        // PRNG (partitionable): rng = fold_in(key(42), layer); k2 = split[1]
        uint32_t f0, f1, k2a, k2b;
        threefry2x32(0u, 42u, 0u, (uint32_t)layer, &f0, &f1);
        threefry2x32(f0, f1, 0u, 1u, &k2a, &k2b);
        int nidx = L * U;
        idx_kernel<<<(nidx + 255) / 256, 256>>>(k2a, k2b, nidx, (unsigned)(L - 1), IDXb);

        int warps = NROW * L;
        msample_kernel<<<(warps * 32 + 255) / 256, 256>>>(Qb, Kb, IDXb, Mb, L, U);
        topk_kernel<<<NROW, 256>>>(Mb, TOPb, L, U);
        vmean_kernel<<<NROW, 256>>>(Vb, VMb, L);
        ofill_kernel<<<(Mrows * 512 + 255) / 256, 256>>>(VMb, Ob, Mrows * 512, L);

        // flash attention over selected queries (split-K + merge)
        {
            int keys = 512;
            int nsplit = L / keys;           // 4, 2, 1
            dim3 ag(nsplit, NROW);
            attn_kernel<<<ag, 256, attn_smem>>>(Qb, Kb, Vb, TOPb,
                                                PMb, PSb, PAb, L, U, keys);
            int mw = NROW * U;
            attn_merge<<<(mw * 32 + 255) / 256, 256>>>(PMb, PSb, PAb, TOPb,
                                                       Ob, L, U, nsplit);
        }

        // out-proj + residual, LN1, FFN(GELU), residual, LN2
        sgemm_kernel<<<gg, 256>>>(Ob, wo, bo + layer * 512, X, nullptr, nullptr,
                                  Yb, 512, 512, FLAG_BIAS | FLAG_RES);
        ln_kernel<<<Mrows, 128>>>(Yb, ln1g + layer * 512, ln1b + layer * 512, XN);
        sgemm_kernel<<<gg, 256>>>(XN, w1, b1 + layer * 512, nullptr, nullptr, nullptr,
                                  H1b, 512, 512, FLAG_BIAS | FLAG_GELU);
        sgemm_kernel<<<gg, 256>>>(H1b, w2, b2 + layer * 512, XN, nullptr, nullptr,
                                  Yb, 512, 512, FLAG_BIAS | FLAG_RES);
        ln_kernel<<<Mrows, 128>>>(Yb, ln2g + layer * 512, ln2b + layer * 512, X);

        // conv distill (ELU fused into GEMM epilogue)
        if (layer < 2) {
            wtrans_kernel<<<(512 * 1536 + 255) / 256, 256>>>(cvw + (size_t)layer * 512 * 1536, WCb);
            xcat_kernel<<<Mrows, 128>>>(X, XC, L);
            sgemm_kernel<<<gg, 256>>>(XC, WCb, cvb + layer * 512, nullptr,
                                      bng + layer * 512, bnb + layer * 512,
                                      CVb, 512, 1536, FLAG_BIAS | FLAG_ELU);
            int Lh = L / 2;
            pool_kernel<<<(BATCH * Lh * 512 + 255) / 256, 256>>>(CVb, X, L);
            L = Lh;
        }
    }

    // final layer norm -> output (4, 512, 512)
    ln_kernel<<<BATCH * L, 128>>>(X, ngp, nbp, (float*)d_out);
}

// round 7
// speedup vs baseline: 1.5329x; 1.0920x over previous
#include <cuda_runtime.h>
#include <stdint.h>
#include <math.h>

// ---------------------------------------------------------------------------
// InformerEncoder: B=4, L0=2048, C=2, D=512, F=512, H=8, dh=64, EL=3
// Numerics: exact fp32 model (R4/R5 passed at 6.2e-6). GEMMs now run on
// tensor cores via mma.sync tf32 with 3xTF32 emulation (hi/lo split), whose
// residual (~2^-22 rel) matches fp32 accumulation-reorder noise.
// PE via double transcendentals; jax_threefry_partitionable PRNG.
// ---------------------------------------------------------------------------
#define D_MODEL 512
#define BATCH   4
#define LMAX    2048
#define NH      8
#define DH      64
#define UMAX    40
#define NROW    (BATCH*NH)      // 32
#define APAD    65              // padded row stride in attn smem
#define SMS     20              // smem row stride (16 k + 4 pad), 16B-aligned

#define FLAG_BIAS 1
#define FLAG_RES  2
#define FLAG_GELU 4
#define FLAG_ELU  8

// ------------------------- scratch (static device globals) ------------------
__device__ float g_X   [BATCH*LMAX*D_MODEL];
__device__ float g_XN  [BATCH*LMAX*D_MODEL];
__device__ float g_Y   [BATCH*LMAX*D_MODEL];
__device__ float g_Q   [BATCH*LMAX*D_MODEL];
__device__ float g_K   [BATCH*LMAX*D_MODEL];
__device__ float g_V   [BATCH*LMAX*D_MODEL];
__device__ float g_O   [BATCH*LMAX*D_MODEL];
__device__ float g_H1  [BATCH*LMAX*D_MODEL];
__device__ float g_XC  [BATCH*LMAX*3*D_MODEL];
__device__ float g_CV  [BATCH*LMAX*D_MODEL];
__device__ float g_WC  [D_MODEL*3*D_MODEL];
__device__ float g_PE  [LMAX*D_MODEL];
__device__ int   g_IDX [LMAX*UMAX];
__device__ float g_M   [NROW*LMAX];
__device__ int   g_TOP [NROW*UMAX];
__device__ float g_VM  [NROW*DH];
__device__ float g_PM  [4*NROW*UMAX];
__device__ float g_PS  [4*NROW*UMAX];
__device__ float g_PA  [4*NROW*UMAX*DH];

// ------------------------- threefry2x32 (JAX-compatible) --------------------
__host__ __device__ inline void threefry2x32(uint32_t k0, uint32_t k1,
                                             uint32_t x0, uint32_t x1,
                                             uint32_t* o0, uint32_t* o1)
{
    uint32_t ks0 = k0, ks1 = k1, ks2 = k0 ^ k1 ^ 0x1BD11BDAu;
    uint32_t ks[3] = {ks0, ks1, ks2};
    x0 += ks0; x1 += ks1;
    const int rA[4] = {13, 15, 26, 6};
    const int rB[4] = {17, 29, 16, 24};
    #pragma unroll
    for (int g = 0; g < 5; ++g) {
        const int* r = (g & 1) ? rB : rA;
        #pragma unroll
        for (int i = 0; i < 4; ++i) {
            x0 += x1;
            x1 = (x1 << r[i]) | (x1 >> (32 - r[i]));
            x1 ^= x0;
        }
        x0 += ks[(g + 1) % 3];
        x1 += ks[(g + 2) % 3] + (uint32_t)(g + 1);
    }
    *o0 = x0; *o1 = x1;
}

// partitionable random_bits: counter (0, j); draw = out0 ^ out1
__global__ void idx_kernel(uint32_t k0, uint32_t k1, int n, unsigned mask,
                           int* __restrict__ idx)
{
    int j = blockIdx.x * blockDim.x + threadIdx.x;
    if (j >= n) return;
    uint32_t o0, o1;
    threefry2x32(k0, k1, 0u, (uint32_t)j, &o0, &o1);
    idx[j] = (int)((o0 ^ o1) & mask);
}

// ------------------------- tensor-core GEMM (3xTF32) ------------------------
__device__ __forceinline__ float gelu_exact(float x)
{
    return 0.5f * x * (1.0f + erff(x * 0.70710678118654752f));
}

__device__ __forceinline__ uint32_t tf32h(float x)
{
    uint32_t u;
    asm("cvt.rna.tf32.f32 %0, %1;" : "=r"(u) : "f"(x));
    return u;
}

__device__ __forceinline__ void mma8(float* c, const uint32_t* a,
                                     const uint32_t* b)
{
    asm volatile(
        "mma.sync.aligned.m16n8k8.row.col.f32.tf32.tf32.f32 "
        "{%0,%1,%2,%3}, {%4,%5,%6,%7}, {%8,%9}, {%0,%1,%2,%3};\n"
        : "+f"(c[0]), "+f"(c[1]), "+f"(c[2]), "+f"(c[3])
        : "r"(a[0]), "r"(a[1]), "r"(a[2]), "r"(a[3]), "r"(b[0]), "r"(b[1]));
}

// C = A @ W^T (+bias)(+R)(gelu)(elu). A: MxK row-major, W: NxK row-major.
// Block tile 128x128, BK=16, 256 thr = 8 warps (2x4), each warp 64m x 32n.
__device__ __forceinline__ void gemm_tile(
    const float* __restrict__ A, const float* __restrict__ W,
    const float* __restrict__ bias, const float* __restrict__ R,
    const float* __restrict__ eg, const float* __restrict__ eb,
    float* __restrict__ C, int N, int K, int flags, int bx, int by)
{
    __shared__ float As[2][128][SMS];
    __shared__ float Ws[2][128][SMS];
    const int t    = threadIdx.x;
    const int lane = t & 31;
    const int warp = t >> 5;
    const int wm   = warp >> 2;      // 0..1
    const int wn   = warp & 3;       // 0..3
    const int g4   = lane >> 2;      // 0..7
    const int tg   = lane & 3;       // 0..3

    const int lrow = t >> 1;
    const int lk   = (t & 1) << 3;

    const float* Ab = A + (size_t)by * 128 * K + (size_t)lrow * K + lk;
    const float* Wb = W + (size_t)bx * 128 * K + (size_t)lrow * K + lk;

    float Cf[4][4][4];
    #pragma unroll
    for (int i = 0; i < 4; i++)
        #pragma unroll
        for (int j = 0; j < 4; j++)
            #pragma unroll
            for (int c = 0; c < 4; c++) Cf[i][j][c] = 0.f;

    float4 pa0 = *(const float4*)(Ab + 0);
    float4 pa1 = *(const float4*)(Ab + 4);
    float4 pw0 = *(const float4*)(Wb + 0);
    float4 pw1 = *(const float4*)(Wb + 4);
    *(float4*)&As[0][lrow][lk]     = pa0;
    *(float4*)&As[0][lrow][lk + 4] = pa1;
    *(float4*)&Ws[0][lrow][lk]     = pw0;
    *(float4*)&Ws[0][lrow][lk + 4] = pw1;
    __syncthreads();

    const int nb = K >> 4;
    for (int kb = 0; kb < nb; kb++) {
        const int cur = kb & 1;
        if (kb + 1 < nb) {
            const float* An = Ab + (size_t)(kb + 1) * 16;
            const float* Wn = Wb + (size_t)(kb + 1) * 16;
            pa0 = *(const float4*)(An + 0);
            pa1 = *(const float4*)(An + 4);
            pw0 = *(const float4*)(Wn + 0);
            pw1 = *(const float4*)(Wn + 4);
        }
        #pragma unroll
        for (int ks = 0; ks < 2; ks++) {
            const int ko = ks << 3;
            uint32_t ah[4][4], al[4][4];
            #pragma unroll
            for (int mt = 0; mt < 4; mt++) {
                const int r = (wm << 6) + (mt << 4) + g4;
                float x0 = As[cur][r    ][ko + tg];
                float x1 = As[cur][r + 8][ko + tg];
                float x2 = As[cur][r    ][ko + tg + 4];
                float x3 = As[cur][r + 8][ko + tg + 4];
                ah[mt][0] = tf32h(x0);
                al[mt][0] = tf32h(x0 - __uint_as_float(ah[mt][0]));
                ah[mt][1] = tf32h(x1);
                al[mt][1] = tf32h(x1 - __uint_as_float(ah[mt][1]));
                ah[mt][2] = tf32h(x2);
                al[mt][2] = tf32h(x2 - __uint_as_float(ah[mt][2]));
                ah[mt][3] = tf32h(x3);
                al[mt][3] = tf32h(x3 - __uint_as_float(ah[mt][3]));
            }
            uint32_t bh[4][2], bl[4][2];
            #pragma unroll
            for (int nt = 0; nt < 4; nt++) {
                const int c = (wn << 5) + (nt << 3) + g4;
                float y0 = Ws[cur][c][ko + tg];
                float y1 = Ws[cur][c][ko + tg + 4];
                bh[nt][0] = tf32h(y0);
                bl[nt][0] = tf32h(y0 - __uint_as_float(bh[nt][0]));
                bh[nt][1] = tf32h(y1);
                bl[nt][1] = tf32h(y1 - __uint_as_float(bh[nt][1]));
            }
            #pragma unroll
            for (int mt = 0; mt < 4; mt++)
                #pragma unroll
                for (int nt = 0; nt < 4; nt++) {
                    mma8(Cf[mt][nt], al[mt], bh[nt]);   // lo*hi
                    mma8(Cf[mt][nt], ah[mt], bl[nt]);   // hi*lo
                    mma8(Cf[mt][nt], ah[mt], bh[nt]);   // hi*hi
                }
        }
        if (kb + 1 < nb) {
            const int nxt = cur ^ 1;
            *(float4*)&As[nxt][lrow][lk]     = pa0;
            *(float4*)&As[nxt][lrow][lk + 4] = pa1;
            *(float4*)&Ws[nxt][lrow][lk]     = pw0;
            *(float4*)&Ws[nxt][lrow][lk + 4] = pw1;
        }
        __syncthreads();
    }

    // epilogue: per fragment, thread owns 2x2 floats as two float2 pairs
    #pragma unroll
    for (int nt = 0; nt < 4; nt++) {
        const int col = bx * 128 + (wn << 5) + (nt << 3) + (tg << 1);
        float2 bz = make_float2(0.f, 0.f);
        if (flags & FLAG_BIAS) bz = *(const float2*)(bias + col);
        float2 gg = make_float2(0.f, 0.f), ee = gg;
        if (flags & FLAG_ELU) {
            gg = *(const float2*)(eg + col);
            ee = *(const float2*)(eb + col);
        }
        #pragma unroll
        for (int mt = 0; mt < 4; mt++) {
            const int row0 = by * 128 + (wm << 6) + (mt << 4) + g4;
            #pragma unroll
            for (int hrow = 0; hrow < 2; hrow++) {
                const int row = row0 + hrow * 8;
                float v0 = Cf[mt][nt][hrow * 2 + 0] + bz.x;
                float v1 = Cf[mt][nt][hrow * 2 + 1] + bz.y;
                if (flags & FLAG_RES) {
                    float2 rr = *(const float2*)(R + (size_t)row * N + col);
                    v0 += rr.x; v1 += rr.y;
                }
                if (flags & FLAG_GELU) {
                    v0 = gelu_exact(v0); v1 = gelu_exact(v1);
                }
                if (flags & FLAG_ELU) {
                    const float cst = 0.9999950000374997f;   // 1/sqrt(1+1e-5)
                    v0 = v0 * cst * gg.x + ee.x;
                    v1 = v1 * cst * gg.y + ee.y;
                    v0 = v0 > 0.f ? v0 : expm1f(v0);
                    v1 = v1 > 0.f ? v1 : expm1f(v1);
                }
                *(float2*)(C + (size_t)row * N + col) = make_float2(v0, v1);
            }
        }
    }
}

__global__ __launch_bounds__(256)
void sgemm_kernel(const float* __restrict__ A, const float* __restrict__ W,
                  const float* __restrict__ bias, const float* __restrict__ R,
                  const float* __restrict__ eg, const float* __restrict__ eb,
                  float* __restrict__ C, int N, int K, int flags)
{
    gemm_tile(A, W, bias, R, eg, eb, C, N, K, flags, blockIdx.x, blockIdx.y);
}

__global__ __launch_bounds__(256)
void qkv_kernel(const float* __restrict__ A,
                const float* __restrict__ wq, const float* __restrict__ wk,
                const float* __restrict__ wv,
                const float* __restrict__ bq, const float* __restrict__ bk,
                const float* __restrict__ bv,
                float* __restrict__ Qo, float* __restrict__ Ko,
                float* __restrict__ Vo, int K)
{
    int which = blockIdx.z;
    const float* W = which == 0 ? wq : (which == 1 ? wk : wv);
    const float* B = which == 0 ? bq : (which == 1 ? bk : bv);
    float*       C = which == 0 ? Qo : (which == 1 ? Ko : Vo);
    gemm_tile(A, W, B, nullptr, nullptr, nullptr, C, 512, K, FLAG_BIAS,
              blockIdx.x, blockIdx.y);
}

// ------------------------- PE table + embedding -----------------------------
__global__ void pe_kernel(float* __restrict__ PE)
{
    int i = blockIdx.x * blockDim.x + threadIdx.x;
    if (i >= LMAX * D_MODEL) return;
    int d = i & 511;
    int l = i >> 9;
    int kk = d >> 1;
    float prod = (float)(2 * kk) * -0.017988946039015984f;
    float divf = (float)exp((double)prod);
    float angf = (float)l * divf;
    PE[i] = (d & 1) ? (float)cos((double)angf) : (float)sin((double)angf);
}

__global__ void embed_kernel(const float* __restrict__ xe,
                             const float* __restrict__ w,
                             const float* __restrict__ PE,
                             float* __restrict__ X)
{
    int i = blockIdx.x * blockDim.x + threadIdx.x;
    if (i >= BATCH * LMAX * D_MODEL) return;
    int d = i & 511;
    int l = (i >> 9) & (LMAX - 1);
    int b = i >> 20;
    float acc = 0.f;
    #pragma unroll
    for (int j = 0; j < 3; j++) {
        int ls = l + j - 1;
        if (ls < 0) ls += LMAX; else if (ls >= LMAX) ls -= LMAX;
        const float* xr = xe + ((size_t)b * LMAX + ls) * 2;
        acc += xr[0] * w[d * 6 + j] + xr[1] * w[d * 6 + 3 + j];
    }
    X[i] = acc + PE[i & (LMAX * D_MODEL - 1)];
}

// ------------------------- M = max_j(Q.K_idx) - sum_j(Q.K_idx)/L -------------
__global__ void msample_kernel(const float* __restrict__ Q,
                               const float* __restrict__ K,
                               const int* __restrict__ idx,
                               float* __restrict__ M, int L, int U)
{
    int w    = (blockIdx.x * blockDim.x + threadIdx.x) >> 5;
    int lane = threadIdx.x & 31;
    int total = NROW * L;
    if (w >= total) return;
    int l = w % L;
    int h = (w / L) % NH;
    int b = w / (L * NH);
    const float* qp = Q + ((size_t)b * L + l) * D_MODEL + h * DH;
    float q0 = qp[lane], q1 = qp[lane + 32];
    float mx = -3.4e38f, sm = 0.f;
    #pragma unroll 4
    for (int j = 0; j < U; j++) {
        int ki = idx[l * U + j];
        const float* kp = K + ((size_t)b * L + ki) * D_MODEL + h * DH;
        float p = q0 * kp[lane] + q1 * kp[lane + 32];
        #pragma unroll
        for (int o = 16; o > 0; o >>= 1) p += __shfl_xor_sync(0xffffffffu, p, o);
        mx = fmaxf(mx, p);
        sm += p;
    }
    if (lane == 0) M[((size_t)b * NH + h) * L + l] = mx - sm / (float)L;
}

// ------------------------- top-u selection (set semantics) ------------------
__global__ void topk_kernel(const float* __restrict__ M, int* __restrict__ top,
                            int L, int U)
{
    __shared__ float vals[LMAX];
    __shared__ unsigned char flags[LMAX];
    __shared__ float rv[256];
    __shared__ int   ri[256];
    int row = blockIdx.x;
    int t   = threadIdx.x;
    const float* mrow = M + (size_t)row * L;
    for (int l = t; l < L; l += 256) { vals[l] = mrow[l]; flags[l] = 0; }
    __syncthreads();
    for (int pass = 0; pass < U; pass++) {
        float bv = -3.4e38f; int bi = 0x7fffffff;
        for (int l = t; l < L; l += 256) {
            if (!flags[l]) {
                float v = vals[l];
                if (v > bv || (v == bv && l < bi)) { bv = v; bi = l; }
            }
        }
        rv[t] = bv; ri[t] = bi;
        __syncthreads();
        for (int s = 128; s > 0; s >>= 1) {
            if (t < s) {
                float ov = rv[t + s]; int oi = ri[t + s];
                if (ov > rv[t] || (ov == rv[t] && oi < ri[t])) { rv[t] = ov; ri[t] = oi; }
            }
            __syncthreads();
        }
        if (t == 0) { top[row * UMAX + pass] = ri[0]; flags[ri[0]] = 1; }
        __syncthreads();
    }
}

// ------------------------- V mean over L ------------------------------------
__global__ void vmean_kernel(const float* __restrict__ V, float* __restrict__ vm,
                             int L)
{
    __shared__ float red[256];
    int row = blockIdx.x;
    int b = row / NH, h = row % NH;
    int t = threadIdx.x;
    int e = t & 63, grp = t >> 6;
    float acc = 0.f;
    for (int l = grp; l < L; l += 4)
        acc += V[((size_t)b * L + l) * D_MODEL + h * DH + e];
    red[t] = acc;
    __syncthreads();
    if (t < 64)
        vm[(size_t)row * DH + t] =
            (red[t] + red[t + 64] + red[t + 128] + red[t + 192]) / (float)L;
}

__global__ void ofill_kernel(const float* __restrict__ vm, float* __restrict__ O,
                             int n, int L)
{
    int i = blockIdx.x * blockDim.x + threadIdx.x;
    if (i >= n) return;
    int d = i & 511;
    int b = i / (L * 512);
    O[i] = vm[(b * NH + (d >> 6)) * 64 + (d & 63)];
}

// ------------------------- flash-style attention ----------------------------
__global__ void attn_kernel(const float* __restrict__ Q,
                            const float* __restrict__ K,
                            const float* __restrict__ V,
                            const int* __restrict__ top,
                            float* __restrict__ PM, float* __restrict__ PS,
                            float* __restrict__ PA,
                            int L, int U, int keys)
{
    extern __shared__ float smf[];
    float* qs = smf;                          // UMAX*APAD
    float* P  = qs + UMAX * APAD;             // UMAX*APAD (scores -> probs)
    float* Kt = P  + UMAX * APAD;             // 64*APAD
    float* Vt = Kt + 64 * APAD;               // 64*APAD
    __shared__ int qidx[UMAX];

    int split = blockIdx.x;
    int row   = blockIdx.y;                   // b*NH+h
    int b = row / NH, h = row % NH;
    int t = threadIdx.x, lane = t & 31, w = t >> 5;

    if (t < U) qidx[t] = top[row * UMAX + t];
    __syncthreads();
    for (int p = t; p < U * 64; p += 256) {
        int j = p >> 6, e = p & 63;
        qs[j * APAD + e] = Q[((size_t)(b * L + qidx[j])) * D_MODEL + h * DH + e];
    }

    float m0[5], s0[5], a0[5], a1[5];
    #pragma unroll
    for (int r = 0; r < 5; r++) { m0[r] = -3.4e38f; s0[r] = 0.f; a0[r] = 0.f; a1[r] = 0.f; }
    __syncthreads();

    int base0 = split * keys;
    int ntile = keys >> 6;
    for (int tl = 0; tl < ntile; tl++) {
        int kb = base0 + (tl << 6);
        for (int i = t; i < 1024; i += 256) {
            int r = i >> 4, c = (i & 15) << 2;
            size_t gi = ((size_t)(b * L + kb + r)) * D_MODEL + h * DH + c;
            float4 kv = *(const float4*)(K + gi);
            float* dk = &Kt[r * APAD + c];
            dk[0] = kv.x; dk[1] = kv.y; dk[2] = kv.z; dk[3] = kv.w;
            float4 vv = *(const float4*)(V + gi);
            float* dv = &Vt[r * APAD + c];
            dv[0] = vv.x; dv[1] = vv.y; dv[2] = vv.z; dv[3] = vv.w;
        }
        __syncthreads();

        {
            float d0[5], d1[5];
            #pragma unroll
            for (int r = 0; r < 5; r++) { d0[r] = 0.f; d1[r] = 0.f; }
            const float* k0 = &Kt[lane * APAD];
            const float* k1 = &Kt[(lane + 32) * APAD];
            #pragma unroll 8
            for (int e = 0; e < 64; e++) {
                float ke0 = k0[e], ke1 = k1[e];
                #pragma unroll
                for (int r = 0; r < 5; r++) {
                    float qe = qs[(w + (r << 3)) * APAD + e];
                    d0[r] += qe * ke0;
                    d1[r] += qe * ke1;
                }
            }
            #pragma unroll
            for (int r = 0; r < 5; r++) {
                int j = w + (r << 3);
                if (j < U) {
                    P[j * APAD + lane]      = d0[r] * 0.125f;
                    P[j * APAD + lane + 32] = d1[r] * 0.125f;
                }
            }
        }
        __syncwarp();

        #pragma unroll
        for (int r = 0; r < 5; r++) {
            int j = w + (r << 3);
            if (j >= U) break;
            float v0 = P[j * APAD + lane], v1 = P[j * APAD + lane + 32];
            float tm = fmaxf(v0, v1);
            #pragma unroll
            for (int o = 16; o > 0; o >>= 1)
                tm = fmaxf(tm, __shfl_xor_sync(0xffffffffu, tm, o));
            float nm = fmaxf(m0[r], tm);
            float p0 = expf(v0 - nm), p1 = expf(v1 - nm);
            float ts = p0 + p1;
            #pragma unroll
            for (int o = 16; o > 0; o >>= 1)
                ts += __shfl_xor_sync(0xffffffffu, ts, o);
            float al = expf(m0[r] - nm);
            s0[r] = s0[r] * al + ts;
            a0[r] *= al; a1[r] *= al;
            m0[r] = nm;
            P[j * APAD + lane]      = p0;
            P[j * APAD + lane + 32] = p1;
        }
        __syncthreads();

        #pragma unroll 4
        for (int k = 0; k < 64; k++) {
            float ve0 = Vt[k * APAD + lane];
            float ve1 = Vt[k * APAD + lane + 32];
            #pragma unroll
            for (int r = 0; r < 5; r++) {
                float pk = P[(w + (r << 3)) * APAD + k];
                a0[r] += pk * ve0;
                a1[r] += pk * ve1;
            }
        }
        __syncthreads();
    }

    #pragma unroll
    for (int r = 0; r < 5; r++) {
        int j = w + (r << 3);
        if (j >= U) break;
        int pidx = (split * NROW + row) * UMAX + j;
        if (lane == 0) { PM[pidx] = m0[r]; PS[pidx] = s0[r]; }
        PA[(size_t)pidx * 64 + lane]      = a0[r];
        PA[(size_t)pidx * 64 + lane + 32] = a1[r];
    }
}

__global__ void attn_merge(const float* __restrict__ PM,
                           const float* __restrict__ PS,
                           const float* __restrict__ PA,
                           const int* __restrict__ top,
                           float* __restrict__ O, int L, int U, int nsplit)
{
    int gw = (blockIdx.x * blockDim.x + threadIdx.x) >> 5;
    int lane = threadIdx.x & 31;
    if (gw >= NROW * U) return;
    int row = gw / U, j = gw % U;
    int b = row / NH, h = row % NH;
    float M = -3.4e38f;
    for (int i = 0; i < nsplit; i++)
        M = fmaxf(M, PM[(i * NROW + row) * UMAX + j]);
    float s = 0.f, acc0 = 0.f, acc1 = 0.f;
    for (int i = 0; i < nsplit; i++) {
        int pidx = (i * NROW + row) * UMAX + j;
        float sc = expf(PM[pidx] - M);
        s    += PS[pidx] * sc;
        acc0 += PA[(size_t)pidx * 64 + lane] * sc;
        acc1 += PA[(size_t)pidx * 64 + lane + 32] * sc;
    }
    float inv = 1.f / s;
    int qi = top[row * UMAX + j];
    size_t o = ((size_t)(b * L + qi)) * D_MODEL + h * DH;
    O[o + lane]      = acc0 * inv;
    O[o + lane + 32] = acc1 * inv;
}

// ------------------------- LayerNorm (two-pass variance) --------------------
__global__ void ln_kernel(const float* __restrict__ X, const float* __restrict__ g,
                          const float* __restrict__ b, float* __restrict__ Y)
{
    __shared__ float s1[4], s2[4];
    int row = blockIdx.x, t = threadIdx.x;
    const float4 v = ((const float4*)(X + (size_t)row * D_MODEL))[t];
    float s = v.x + v.y + v.z + v.w;
    #pragma unroll
    for (int o = 16; o > 0; o >>= 1) s += __shfl_xor_sync(0xffffffffu, s, o);
    if ((t & 31) == 0) s1[t >> 5] = s;
    __syncthreads();
    float mean = (s1[0] + s1[1] + s1[2] + s1[3]) * (1.f / 512.f);
    float dx = v.x - mean, dy = v.y - mean, dz = v.z - mean, dw = v.w - mean;
    float ss = dx * dx + dy * dy + dz * dz + dw * dw;
    #pragma unroll
    for (int o = 16; o > 0; o >>= 1) ss += __shfl_xor_sync(0xffffffffu, ss, o);
    if ((t & 31) == 0) s2[t >> 5] = ss;
    __syncthreads();
    float var = (s2[0] + s2[1] + s2[2] + s2[3]) * (1.f / 512.f);
    float inv = 1.f / sqrtf(var + 1e-5f);
    const float4 g4 = ((const float4*)g)[t];
    const float4 b4 = ((const float4*)b)[t];
    float4 o;
    o.x = dx * inv * g4.x + b4.x;
    o.y = dy * inv * g4.y + b4.y;
    o.z = dz * inv * g4.z + b4.z;
    o.w = dw * inv * g4.w + b4.w;
    ((float4*)(Y + (size_t)row * D_MODEL))[t] = o;
}

// ------------------------- conv-distill helpers -----------------------------
__global__ void wtrans_kernel(const float* __restrict__ cv, float* __restrict__ WC)
{
    int i = blockIdx.x * blockDim.x + threadIdx.x;
    if (i >= D_MODEL * 3 * D_MODEL) return;
    int n = i / 1536, k = i % 1536;
    int j = k / 512, c = k % 512;
    WC[i] = cv[(size_t)n * 1536 + c * 3 + j];
}

__global__ void xcat_kernel(const float* __restrict__ X, float* __restrict__ XC,
                            int L)
{
    int m = blockIdx.x;
    int t = threadIdx.x;
    int b = m / L, l = m % L;
    float4* dst = (float4*)(XC + (size_t)m * 1536);
    #pragma unroll
    for (int r = 0; r < 3; r++) {
        int ls = l + r - 1;
        if (ls < 0) ls += L; else if (ls >= L) ls -= L;
        dst[r * 128 + t] = ((const float4*)(X + ((size_t)b * L + ls) * 512))[t];
    }
}

__global__ void pool_kernel(const float* __restrict__ Y, float* __restrict__ X,
                            int L)
{
    int Lh = L >> 1;
    int i = blockIdx.x * blockDim.x + threadIdx.x;
    if (i >= BATCH * Lh * 512) return;
    int d = i & 511;
    int m = (i >> 9) % Lh;
    int b = i / (Lh * 512);
    const float* yb = Y + (size_t)b * L * 512 + d;
    float v = fmaxf(yb[(size_t)(2 * m) * 512], yb[(size_t)(2 * m + 1) * 512]);
    if (m > 0) v = fmaxf(v, yb[(size_t)(2 * m - 1) * 512]);
    X[i] = v;
}

// ---------------------------------------------------------------------------
extern "C" void kernel_launch(void* const* d_in, const int* in_sizes, int n_in,
                              void* d_out, int out_size)
{
    (void)in_sizes; (void)n_in; (void)out_size;
    const float* x_enc = (const float*)d_in[0];
    const float* emb_w = (const float*)d_in[1];
    const float* Wq  = (const float*)d_in[2];
    const float* bq  = (const float*)d_in[3];
    const float* Wk  = (const float*)d_in[4];
    const float* bk  = (const float*)d_in[5];
    const float* Wv  = (const float*)d_in[6];
    const float* bv  = (const float*)d_in[7];
    const float* Wo  = (const float*)d_in[8];
    const float* bo  = (const float*)d_in[9];
    const float* ln1g = (const float*)d_in[10];
    const float* ln1b = (const float*)d_in[11];
    const float* W1  = (const float*)d_in[12];
    const float* b1  = (const float*)d_in[13];
    const float* W2  = (const float*)d_in[14];
    const float* b2  = (const float*)d_in[15];
    const float* ln2g = (const float*)d_in[16];
    const float* ln2b = (const float*)d_in[17];
    const float* cvw = (const float*)d_in[18];
    const float* cvb = (const float*)d_in[19];
    const float* bng = (const float*)d_in[20];
    const float* bnb = (const float*)d_in[21];
    const float* ngp = (const float*)d_in[22];
    const float* nbp = (const float*)d_in[23];

    float *X, *XN, *Yb, *Qb, *Kb, *Vb, *Ob, *H1b, *XC, *CVb, *WCb, *Mb, *VMb;
    float *PEb, *PMb, *PSb, *PAb;
    int *IDXb, *TOPb;
    cudaGetSymbolAddress((void**)&X,   g_X);
    cudaGetSymbolAddress((void**)&XN,  g_XN);
    cudaGetSymbolAddress((void**)&Yb,  g_Y);
    cudaGetSymbolAddress((void**)&Qb,  g_Q);
    cudaGetSymbolAddress((void**)&Kb,  g_K);
    cudaGetSymbolAddress((void**)&Vb,  g_V);
    cudaGetSymbolAddress((void**)&Ob,  g_O);
    cudaGetSymbolAddress((void**)&H1b, g_H1);
    cudaGetSymbolAddress((void**)&XC,  g_XC);
    cudaGetSymbolAddress((void**)&CVb, g_CV);
    cudaGetSymbolAddress((void**)&WCb, g_WC);
    cudaGetSymbolAddress((void**)&PEb, g_PE);
    cudaGetSymbolAddress((void**)&Mb,  g_M);
    cudaGetSymbolAddress((void**)&VMb, g_VM);
    cudaGetSymbolAddress((void**)&PMb, g_PM);
    cudaGetSymbolAddress((void**)&PSb, g_PS);
    cudaGetSymbolAddress((void**)&PAb, g_PA);
    cudaGetSymbolAddress((void**)&IDXb, g_IDX);
    cudaGetSymbolAddress((void**)&TOPb, g_TOP);

    const int attn_smem = (UMAX * APAD * 2 + 64 * APAD * 2) * 4;   // 54080 B
    cudaFuncSetAttribute(attn_kernel,
                         cudaFuncAttributeMaxDynamicSharedMemorySize, attn_smem);

    // PE table + embedding
    pe_kernel<<<(LMAX * D_MODEL + 255) / 256, 256>>>(PEb);
    {
        int total = BATCH * LMAX * D_MODEL;
        embed_kernel<<<(total + 255) / 256, 256>>>(x_enc, emb_w, PEb, X);
    }

    int L = LMAX;
    for (int layer = 0; layer < 3; layer++) {
        int U = 5 * (int)ceil(log((double)L));   // 40, 35, 35
        if (U > L) U = L;
        int Mrows = BATCH * L;
        dim3 gg(D_MODEL / 128, Mrows / 128);

        const float* wq = Wq + (size_t)layer * 512 * 512;
        const float* wk = Wk + (size_t)layer * 512 * 512;
        const float* wv = Wv + (size_t)layer * 512 * 512;
        const float* wo = Wo + (size_t)layer * 512 * 512;
        const float* w1 = W1 + (size_t)layer * 512 * 512;
        const float* w2 = W2 + (size_t)layer * 512 * 512;

        // fused QKV projections (3 GEMMs in one launch)
        {
            dim3 gq(D_MODEL / 128, Mrows / 128, 3);
            qkv_kernel<<<gq, 256>>>(X, wq, wk, wv,
                                    bq + layer * 512, bk + layer * 512,
                                    bv + layer * 512, Qb, Kb, Vb, 512);
        }

        // PRNG (partitionable): rng = fold_in(key(42), layer); k2 = split[1]
        uint32_t f0, f1, k2a, k2b;
        threefry2x32(0u, 42u, 0u, (uint32_t)layer, &f0, &f1);
        threefry2x32(f0, f1, 0u, 1u, &k2a, &k2b);
        int nidx = L * U;
        idx_kernel<<<(nidx + 255) / 256, 256>>>(k2a, k2b, nidx, (unsigned)(L - 1), IDXb);

        int warps = NROW * L;
        msample_kernel<<<(warps * 32 + 255) / 256, 256>>>(Qb, Kb, IDXb, Mb, L, U);
        topk_kernel<<<NROW, 256>>>(Mb, TOPb, L, U);
        vmean_kernel<<<NROW, 256>>>(Vb, VMb, L);
        ofill_kernel<<<(Mrows * 512 + 255) / 256, 256>>>(VMb, Ob, Mrows * 512, L);

        // flash attention over selected queries (split-K + merge)
        {
            int keys = 512;
            int nsplit = L / keys;           // 4, 2, 1
            dim3 ag(nsplit, NROW);
            attn_kernel<<<ag, 256, attn_smem>>>(Qb, Kb, Vb, TOPb,
                                                PMb, PSb, PAb, L, U, keys);
            int mw = NROW * U;
            attn_merge<<<(mw * 32 + 255) / 256, 256>>>(PMb, PSb, PAb, TOPb,
                                                       Ob, L, U, nsplit);
        }

        // out-proj + residual, LN1, FFN(GELU), residual, LN2
        sgemm_kernel<<<gg, 256>>>(Ob, wo, bo + layer * 512, X, nullptr, nullptr,
                                  Yb, 512, 512, FLAG_BIAS | FLAG_RES);
        ln_kernel<<<Mrows, 128>>>(Yb, ln1g + layer * 512, ln1b + layer * 512, XN);
        sgemm_kernel<<<gg, 256>>>(XN, w1, b1 + layer * 512, nullptr, nullptr, nullptr,
                                  H1b, 512, 512, FLAG_BIAS | FLAG_GELU);
        sgemm_kernel<<<gg, 256>>>(H1b, w2, b2 + layer * 512, XN, nullptr, nullptr,
                                  Yb, 512, 512, FLAG_BIAS | FLAG_RES);
        ln_kernel<<<Mrows, 128>>>(Yb, ln2g + layer * 512, ln2b + layer * 512, X);

        // conv distill (ELU fused into GEMM epilogue)
        if (layer < 2) {
            wtrans_kernel<<<(512 * 1536 + 255) / 256, 256>>>(cvw + (size_t)layer * 512 * 1536, WCb);
            xcat_kernel<<<Mrows, 128>>>(X, XC, L);
            sgemm_kernel<<<gg, 256>>>(XC, WCb, cvb + layer * 512, nullptr,
                                      bng + layer * 512, bnb + layer * 512,
                                      CVb, 512, 1536, FLAG_BIAS | FLAG_ELU);
            int Lh = L / 2;
            pool_kernel<<<(BATCH * Lh * 512 + 255) / 256, 256>>>(CVb, X, L);
            L = Lh;
        }
    }

    // final layer norm -> output (4, 512, 512)
    ln_kernel<<<BATCH * L, 128>>>(X, ngp, nbp, (float*)d_out);
}

// round 9
// speedup vs baseline: 2.1535x; 1.4048x over previous
#include <cuda_runtime.h>
#include <stdint.h>
#include <math.h>

// ---------------------------------------------------------------------------
// InformerEncoder: B=4, L0=2048, C=2, D=512, F=512, H=8, dh=64, EL=3
// Numerics: exact-fp32 model via 3xTF32 (hi/lo split).
// GEMM backend selected at compile time:
//   sm_103a-specific target (__CUDA_ARCH_FEAT_SM103_ALL) -> tcgen05 (UTCHMMA)
//   generic sm_103 PTX pass                              -> mma.sync HMMA
// PE via double transcendentals; jax_threefry_partitionable PRNG.
// ---------------------------------------------------------------------------
#define D_MODEL 512
#define BATCH   4
#define LMAX    2048
#define NH      8
#define DH      64
#define UMAX    40
#define NROW    (BATCH*NH)
#define APAD    65
#define SMS     20

#define FLAG_BIAS 1
#define FLAG_RES  2
#define FLAG_GELU 4
#define FLAG_ELU  8

#define GEMM_CHUNK 32
#define TILE_B     16384                // one 128x32 fp32 tile in bytes
#define GEMM_SMEM  (1024 + 8*TILE_B)    // align slack + 2 bufs x 4 tiles
// idesc: dtype f32 | atype tf32 | btype tf32 | N=128 | M=128
#define TC_IDESC ((1u<<4)|(2u<<7)|(2u<<10)|((128u/8)<<17)|((128u/16)<<24))

#if defined(__CUDA_ARCH_FEAT_SM103_ALL)
#define HAS_TCGEN05 1
#else
#define HAS_TCGEN05 0
#endif

// ------------------------- scratch (static device globals) ------------------
__device__ float g_X   [BATCH*LMAX*D_MODEL];
__device__ float g_XN  [BATCH*LMAX*D_MODEL];
__device__ float g_Y   [BATCH*LMAX*D_MODEL];
__device__ float g_Q   [BATCH*LMAX*D_MODEL];
__device__ float g_K   [BATCH*LMAX*D_MODEL];
__device__ float g_V   [BATCH*LMAX*D_MODEL];
__device__ float g_O   [BATCH*LMAX*D_MODEL];
__device__ float g_H1  [BATCH*LMAX*D_MODEL];
__device__ float g_XC  [BATCH*LMAX*3*D_MODEL];
__device__ float g_CV  [BATCH*LMAX*D_MODEL];
__device__ float g_WC  [D_MODEL*3*D_MODEL];
__device__ float g_PE  [LMAX*D_MODEL];
__device__ int   g_IDX [LMAX*UMAX];
__device__ float g_M   [NROW*LMAX];
__device__ int   g_TOP [NROW*UMAX];
__device__ float g_VM  [NROW*DH];
__device__ float g_PM  [4*NROW*UMAX];
__device__ float g_PS  [4*NROW*UMAX];
__device__ float g_PA  [4*NROW*UMAX*DH];

// ------------------------- threefry2x32 (JAX-compatible) --------------------
__host__ __device__ inline void threefry2x32(uint32_t k0, uint32_t k1,
                                             uint32_t x0, uint32_t x1,
                                             uint32_t* o0, uint32_t* o1)
{
    uint32_t ks0 = k0, ks1 = k1, ks2 = k0 ^ k1 ^ 0x1BD11BDAu;
    uint32_t ks[3] = {ks0, ks1, ks2};
    x0 += ks0; x1 += ks1;
    const int rA[4] = {13, 15, 26, 6};
    const int rB[4] = {17, 29, 16, 24};
    #pragma unroll
    for (int g = 0; g < 5; ++g) {
        const int* r = (g & 1) ? rB : rA;
        #pragma unroll
        for (int i = 0; i < 4; ++i) {
            x0 += x1;
            x1 = (x1 << r[i]) | (x1 >> (32 - r[i]));
            x1 ^= x0;
        }
        x0 += ks[(g + 1) % 3];
        x1 += ks[(g + 2) % 3] + (uint32_t)(g + 1);
    }
    *o0 = x0; *o1 = x1;
}

__global__ void idx_kernel(uint32_t k0, uint32_t k1, int n, unsigned mask,
                           int* __restrict__ idx)
{
    int j = blockIdx.x * blockDim.x + threadIdx.x;
    if (j >= n) return;
    uint32_t o0, o1;
    threefry2x32(k0, k1, 0u, (uint32_t)j, &o0, &o1);
    idx[j] = (int)((o0 ^ o1) & mask);
}

// ------------------------- common helpers -----------------------------------
__device__ __forceinline__ float gelu_exact(float x)
{
    return 0.5f * x * (1.0f + erff(x * 0.70710678118654752f));
}

__device__ __forceinline__ float tf32f(float x)
{
    uint32_t u;
    asm("cvt.rna.tf32.f32 %0, %1;" : "=r"(u) : "f"(x));
    return __uint_as_float(u);
}

__device__ __forceinline__ uint32_t tf32h(float x)
{
    uint32_t u;
    asm("cvt.rna.tf32.f32 %0, %1;" : "=r"(u) : "f"(x));
    return u;
}

#if HAS_TCGEN05
// ===================== tcgen05 backend (sm_103a target) =====================
__device__ __forceinline__ uint32_t s2u(const void* p)
{
    uint32_t a;
    asm("{ .reg .u64 t; cvta.to.shared.u64 t, %1; cvt.u32.u64 %0, t; }"
        : "=r"(a) : "l"(p));
    return a;
}

__device__ __forceinline__ uint64_t sdesc(uint32_t a)
{
    // SW128 K-major: layout=2, version=1(Blackwell), SBO=64, LBO=1
    return (2ULL << 61) | (1ULL << 46) | (64ULL << 32) | (1ULL << 16)
         | (uint64_t)((a >> 4) & 0x3FFF);
}

__device__ __forceinline__ uint32_t swz(uint32_t b)
{
    return b ^ ((b >> 3) & 0x70);
}

__device__ __forceinline__ void tcmma_tf32(uint32_t d, uint64_t a, uint64_t b,
                                           uint32_t idesc, uint32_t en)
{
    asm volatile(
        "{\n\t"
        ".reg .pred p;\n\t"
        "setp.ne.u32 p, %5, 0;\n\t"
        "tcgen05.mma.cta_group::1.kind::tf32 [%0], %1, %2, %3, {%4,%4,%4,%4}, p;\n\t"
        "}"
        :: "r"(d), "l"(a), "l"(b), "r"(idesc), "r"(0u), "r"(en)
        : "memory");
}

__device__ __forceinline__ void tc_commit(uint32_t mbar)
{
    asm volatile(
        "tcgen05.commit.cta_group::1.mbarrier::arrive::one.shared::cluster.b64 [%0];"
        :: "r"(mbar) : "memory");
}

__device__ __forceinline__ void mbar_wait(uint32_t mbar, uint32_t parity)
{
    asm volatile(
        "{\n\t"
        ".reg .pred P;\n\t"
        "W_%=:\n\t"
        "mbarrier.try_wait.parity.shared.b64 P, [%0], %1;\n\t"
        "@!P bra W_%=;\n\t"
        "}"
        :: "r"(mbar), "r"(parity) : "memory");
}

#define TC_LD_X32(r, addr) \
    asm volatile( \
        "tcgen05.ld.sync.aligned.32x32b.x32.b32 " \
        "{%0, %1, %2, %3, %4, %5, %6, %7, " \
        " %8, %9, %10, %11, %12, %13, %14, %15, " \
        " %16, %17, %18, %19, %20, %21, %22, %23, " \
        " %24, %25, %26, %27, %28, %29, %30, %31}, [%32];" \
        : "=r"((r)[0]),  "=r"((r)[1]),  "=r"((r)[2]),  "=r"((r)[3]), \
          "=r"((r)[4]),  "=r"((r)[5]),  "=r"((r)[6]),  "=r"((r)[7]), \
          "=r"((r)[8]),  "=r"((r)[9]),  "=r"((r)[10]), "=r"((r)[11]), \
          "=r"((r)[12]), "=r"((r)[13]), "=r"((r)[14]), "=r"((r)[15]), \
          "=r"((r)[16]), "=r"((r)[17]), "=r"((r)[18]), "=r"((r)[19]), \
          "=r"((r)[20]), "=r"((r)[21]), "=r"((r)[22]), "=r"((r)[23]), \
          "=r"((r)[24]), "=r"((r)[25]), "=r"((r)[26]), "=r"((r)[27]), \
          "=r"((r)[28]), "=r"((r)[29]), "=r"((r)[30]), "=r"((r)[31]) \
        : "r"(addr))

// C = A @ W^T (+bias)(+R)(gelu)(elu). A: MxK, W: NxK row-major. 128x128 tile.
__device__ __forceinline__ void gemm_tile(
    const float* __restrict__ A, const float* __restrict__ W,
    const float* __restrict__ bias, const float* __restrict__ R,
    const float* __restrict__ eg, const float* __restrict__ eb,
    float* __restrict__ C, int N, int K, int flags, int bx, int by)
{
    extern __shared__ char dsm[];
    __shared__ uint32_t s_tmem[1];
    __shared__ uint64_t s_mbar[2];

    const int t = threadIdx.x;
    const uint32_t daddr = s2u(dsm);
    const uint32_t aoff  = (1024u - (daddr & 1023u)) & 1023u;
    char* tb = dsm + aoff;
    const uint32_t tb_addr = daddr + aoff;

    const uint32_t ctrl = s2u(s_tmem);
    const uint32_t mb0  = s2u(&s_mbar[0]);
    const uint32_t mb1  = s2u(&s_mbar[1]);

    if (t < 32)
        asm volatile(
            "tcgen05.alloc.cta_group::1.sync.aligned.shared::cta.b32 [%0], %1;"
            :: "r"(ctrl), "r"(128u) : "memory");
    if (t == 0) {
        asm volatile("mbarrier.init.shared.b64 [%0], 1;" :: "r"(mb0) : "memory");
        asm volatile("mbarrier.init.shared.b64 [%0], 1;" :: "r"(mb1) : "memory");
    }
    __syncthreads();
    const uint32_t tmem_base = s_tmem[0];

    const float* Abase = A + (size_t)by * 128 * K;
    const float* Wbase = W + (size_t)bx * 128 * K;

    const int nb = K / GEMM_CHUNK;
    int ph0 = 0, ph1 = 0;

    for (int c = 0; c < nb; c++) {
        const int buf = c & 1;
        if (c >= 2) {
            if (buf == 0) { mbar_wait(mb0, (uint32_t)(ph0 & 1)); ph0++; }
            else          { mbar_wait(mb1, (uint32_t)(ph1 & 1)); ph1++; }
        }
        const float* Ac = Abase + (size_t)c * GEMM_CHUNK;
        const float* Wc = Wbase + (size_t)c * GEMM_CHUNK;
        char* bufp = tb + buf * (4 * TILE_B);
        #pragma unroll
        for (int i = 0; i < 4; i++) {
            const int idx = t + i * 256;         // 0..1023
            const int row = idx >> 3, c4 = idx & 7;
            const float4 av = *(const float4*)(Ac + (size_t)row * K + c4 * 4);
            const float4 wv = *(const float4*)(Wc + (size_t)row * K + c4 * 4);
            const uint32_t off = swz((uint32_t)(row * 128 + c4 * 16));
            float4 h, l;
            h.x = tf32f(av.x); l.x = tf32f(av.x - h.x);
            h.y = tf32f(av.y); l.y = tf32f(av.y - h.y);
            h.z = tf32f(av.z); l.z = tf32f(av.z - h.z);
            h.w = tf32f(av.w); l.w = tf32f(av.w - h.w);
            *(float4*)(bufp + off)              = h;
            *(float4*)(bufp + TILE_B + off)     = l;
            h.x = tf32f(wv.x); l.x = tf32f(wv.x - h.x);
            h.y = tf32f(wv.y); l.y = tf32f(wv.y - h.y);
            h.z = tf32f(wv.z); l.z = tf32f(wv.z - h.z);
            h.w = tf32f(wv.w); l.w = tf32f(wv.w - h.w);
            *(float4*)(bufp + 2 * TILE_B + off) = h;
            *(float4*)(bufp + 3 * TILE_B + off) = l;
        }
        asm volatile("fence.proxy.async.shared::cta;" ::: "memory");
        __syncthreads();
        if (t == 0) {
            const uint32_t ba = tb_addr + buf * (4 * TILE_B);
            const uint64_t dah = sdesc(ba);
            const uint64_t dal = sdesc(ba + TILE_B);
            const uint64_t dwh = sdesc(ba + 2 * TILE_B);
            const uint64_t dwl = sdesc(ba + 3 * TILE_B);
            #pragma unroll
            for (int s = 0; s < 4; s++) {
                const uint32_t en0 = (c == 0 && s == 0) ? 0u : 1u;
                tcmma_tf32(tmem_base, dah + s * 2, dwl + s * 2, TC_IDESC, en0);
                tcmma_tf32(tmem_base, dal + s * 2, dwh + s * 2, TC_IDESC, 1u);
                tcmma_tf32(tmem_base, dah + s * 2, dwh + s * 2, TC_IDESC, 1u);
            }
            tc_commit(buf ? mb1 : mb0);
        }
    }

    mbar_wait(mb0, (uint32_t)(ph0 & 1));
    if (nb >= 2) mbar_wait(mb1, (uint32_t)(ph1 & 1));
    asm volatile("tcgen05.fence::after_thread_sync;" ::: "memory");

    // epilogue: warp w covers rows (w&3)*32+lane, cols (w>>2)*64 .. +63
    const int w = t >> 5, lane = t & 31;
    const int rown = (w & 3) * 32 + lane;
    const int colw = (w >> 2) * 64;
    const size_t grow = (size_t)(by * 128 + rown);

    #pragma unroll
    for (int half = 0; half < 2; half++) {
        uint32_t dr[32];
        TC_LD_X32(dr, tmem_base + colw + half * 32);
        asm volatile("tcgen05.wait::ld.sync.aligned;" ::: "memory");
        const int cb = bx * 128 + colw + half * 32;
        float* crow = C + grow * N + cb;
        const float* rrow = (flags & FLAG_RES) ? (R + grow * N + cb) : nullptr;
        #pragma unroll
        for (int q = 0; q < 8; q++) {
            float v0 = __uint_as_float(dr[q * 4 + 0]);
            float v1 = __uint_as_float(dr[q * 4 + 1]);
            float v2 = __uint_as_float(dr[q * 4 + 2]);
            float v3 = __uint_as_float(dr[q * 4 + 3]);
            if (flags & FLAG_BIAS) {
                float4 bz = *(const float4*)(bias + cb + q * 4);
                v0 += bz.x; v1 += bz.y; v2 += bz.z; v3 += bz.w;
            }
            if (flags & FLAG_RES) {
                float4 rr = *(const float4*)(rrow + q * 4);
                v0 += rr.x; v1 += rr.y; v2 += rr.z; v3 += rr.w;
            }
            if (flags & FLAG_GELU) {
                v0 = gelu_exact(v0); v1 = gelu_exact(v1);
                v2 = gelu_exact(v2); v3 = gelu_exact(v3);
            }
            if (flags & FLAG_ELU) {
                const float cst = 0.9999950000374997f;   // 1/sqrt(1+1e-5)
                float4 gv = *(const float4*)(eg + cb + q * 4);
                float4 ev = *(const float4*)(eb + cb + q * 4);
                v0 = v0 * cst * gv.x + ev.x;
                v1 = v1 * cst * gv.y + ev.y;
                v2 = v2 * cst * gv.z + ev.z;
                v3 = v3 * cst * gv.w + ev.w;
                v0 = v0 > 0.f ? v0 : expm1f(v0);
                v1 = v1 > 0.f ? v1 : expm1f(v1);
                v2 = v2 > 0.f ? v2 : expm1f(v2);
                v3 = v3 > 0.f ? v3 : expm1f(v3);
            }
            *(float4*)(crow + q * 4) = make_float4(v0, v1, v2, v3);
        }
    }

    __syncthreads();
    if (t == 0) {
        asm volatile("mbarrier.inval.shared.b64 [%0];" :: "r"(mb0) : "memory");
        asm volatile("mbarrier.inval.shared.b64 [%0];" :: "r"(mb1) : "memory");
    }
    if (t < 32) {
        asm volatile("tcgen05.relinquish_alloc_permit.cta_group::1.sync.aligned;");
        asm volatile("tcgen05.dealloc.cta_group::1.sync.aligned.b32 %0, %1;"
                     :: "r"(tmem_base), "r"(128u));
    }
}

#else
// ===================== HMMA fallback (generic sm_103 PTX) ===================
__device__ __forceinline__ void mma8(float* c, const uint32_t* a,
                                     const uint32_t* b)
{
    asm volatile(
        "mma.sync.aligned.m16n8k8.row.col.f32.tf32.tf32.f32 "
        "{%0,%1,%2,%3}, {%4,%5,%6,%7}, {%8,%9}, {%0,%1,%2,%3};\n"
        : "+f"(c[0]), "+f"(c[1]), "+f"(c[2]), "+f"(c[3])
        : "r"(a[0]), "r"(a[1]), "r"(a[2]), "r"(a[3]), "r"(b[0]), "r"(b[1]));
}

__device__ __forceinline__ void gemm_tile(
    const float* __restrict__ A, const float* __restrict__ W,
    const float* __restrict__ bias, const float* __restrict__ R,
    const float* __restrict__ eg, const float* __restrict__ eb,
    float* __restrict__ C, int N, int K, int flags, int bx, int by)
{
    __shared__ float As[2][128][SMS];
    __shared__ float Ws[2][128][SMS];
    const int t    = threadIdx.x;
    const int lane = t & 31;
    const int warp = t >> 5;
    const int wm   = warp >> 2;
    const int wn   = warp & 3;
    const int g4   = lane >> 2;
    const int tg   = lane & 3;

    const int lrow = t >> 1;
    const int lk   = (t & 1) << 3;

    const float* Ab = A + (size_t)by * 128 * K + (size_t)lrow * K + lk;
    const float* Wb = W + (size_t)bx * 128 * K + (size_t)lrow * K + lk;

    float Cf[4][4][4];
    #pragma unroll
    for (int i = 0; i < 4; i++)
        #pragma unroll
        for (int j = 0; j < 4; j++)
            #pragma unroll
            for (int c = 0; c < 4; c++) Cf[i][j][c] = 0.f;

    float4 pa0 = *(const float4*)(Ab + 0);
    float4 pa1 = *(const float4*)(Ab + 4);
    float4 pw0 = *(const float4*)(Wb + 0);
    float4 pw1 = *(const float4*)(Wb + 4);
    *(float4*)&As[0][lrow][lk]     = pa0;
    *(float4*)&As[0][lrow][lk + 4] = pa1;
    *(float4*)&Ws[0][lrow][lk]     = pw0;
    *(float4*)&Ws[0][lrow][lk + 4] = pw1;
    __syncthreads();

    const int nb = K >> 4;
    for (int kb = 0; kb < nb; kb++) {
        const int cur = kb & 1;
        if (kb + 1 < nb) {
            const float* An = Ab + (size_t)(kb + 1) * 16;
            const float* Wn = Wb + (size_t)(kb + 1) * 16;
            pa0 = *(const float4*)(An + 0);
            pa1 = *(const float4*)(An + 4);
            pw0 = *(const float4*)(Wn + 0);
            pw1 = *(const float4*)(Wn + 4);
        }
        #pragma unroll
        for (int ks = 0; ks < 2; ks++) {
            const int ko = ks << 3;
            uint32_t ah[4][4], al[4][4];
            #pragma unroll
            for (int mt = 0; mt < 4; mt++) {
                const int r = (wm << 6) + (mt << 4) + g4;
                float x0 = As[cur][r    ][ko + tg];
                float x1 = As[cur][r + 8][ko + tg];
                float x2 = As[cur][r    ][ko + tg + 4];
                float x3 = As[cur][r + 8][ko + tg + 4];
                ah[mt][0] = tf32h(x0);
                al[mt][0] = tf32h(x0 - __uint_as_float(ah[mt][0]));
                ah[mt][1] = tf32h(x1);
                al[mt][1] = tf32h(x1 - __uint_as_float(ah[mt][1]));
                ah[mt][2] = tf32h(x2);
                al[mt][2] = tf32h(x2 - __uint_as_float(ah[mt][2]));
                ah[mt][3] = tf32h(x3);
                al[mt][3] = tf32h(x3 - __uint_as_float(ah[mt][3]));
            }
            uint32_t bh[4][2], bl[4][2];
            #pragma unroll
            for (int nt = 0; nt < 4; nt++) {
                const int c = (wn << 5) + (nt << 3) + g4;
                float y0 = Ws[cur][c][ko + tg];
                float y1 = Ws[cur][c][ko + tg + 4];
                bh[nt][0] = tf32h(y0);
                bl[nt][0] = tf32h(y0 - __uint_as_float(bh[nt][0]));
                bh[nt][1] = tf32h(y1);
                bl[nt][1] = tf32h(y1 - __uint_as_float(bh[nt][1]));
            }
            #pragma unroll
            for (int mt = 0; mt < 4; mt++)
                #pragma unroll
                for (int nt = 0; nt < 4; nt++) {
                    mma8(Cf[mt][nt], al[mt], bh[nt]);
                    mma8(Cf[mt][nt], ah[mt], bl[nt]);
                    mma8(Cf[mt][nt], ah[mt], bh[nt]);
                }
        }
        if (kb + 1 < nb) {
            const int nxt = cur ^ 1;
            *(float4*)&As[nxt][lrow][lk]     = pa0;
            *(float4*)&As[nxt][lrow][lk + 4] = pa1;
            *(float4*)&Ws[nxt][lrow][lk]     = pw0;
            *(float4*)&Ws[nxt][lrow][lk + 4] = pw1;
        }
        __syncthreads();
    }

    #pragma unroll
    for (int nt = 0; nt < 4; nt++) {
        const int col = bx * 128 + (wn << 5) + (nt << 3) + (tg << 1);
        float2 bz = make_float2(0.f, 0.f);
        if (flags & FLAG_BIAS) bz = *(const float2*)(bias + col);
        float2 gg = make_float2(0.f, 0.f), ee = gg;
        if (flags & FLAG_ELU) {
            gg = *(const float2*)(eg + col);
            ee = *(const float2*)(eb + col);
        }
        #pragma unroll
        for (int mt = 0; mt < 4; mt++) {
            const int row0 = by * 128 + (wm << 6) + (mt << 4) + g4;
            #pragma unroll
            for (int hrow = 0; hrow < 2; hrow++) {
                const int row = row0 + hrow * 8;
                float v0 = Cf[mt][nt][hrow * 2 + 0] + bz.x;
                float v1 = Cf[mt][nt][hrow * 2 + 1] + bz.y;
                if (flags & FLAG_RES) {
                    float2 rr = *(const float2*)(R + (size_t)row * N + col);
                    v0 += rr.x; v1 += rr.y;
                }
                if (flags & FLAG_GELU) {
                    v0 = gelu_exact(v0); v1 = gelu_exact(v1);
                }
                if (flags & FLAG_ELU) {
                    const float cst = 0.9999950000374997f;
                    v0 = v0 * cst * gg.x + ee.x;
                    v1 = v1 * cst * gg.y + ee.y;
                    v0 = v0 > 0.f ? v0 : expm1f(v0);
                    v1 = v1 > 0.f ? v1 : expm1f(v1);
                }
                *(float2*)(C + (size_t)row * N + col) = make_float2(v0, v1);
            }
        }
    }
}
#endif  // HAS_TCGEN05

__global__ __launch_bounds__(256)
void sgemm_kernel(const float* __restrict__ A, const float* __restrict__ W,
                  const float* __restrict__ bias, const float* __restrict__ R,
                  const float* __restrict__ eg, const float* __restrict__ eb,
                  float* __restrict__ C, int N, int K, int flags)
{
    gemm_tile(A, W, bias, R, eg, eb, C, N, K, flags, blockIdx.x, blockIdx.y);
}

__global__ __launch_bounds__(256)
void qkv_kernel(const float* __restrict__ A,
                const float* __restrict__ wq, const float* __restrict__ wk,
                const float* __restrict__ wv,
                const float* __restrict__ bq, const float* __restrict__ bk,
                const float* __restrict__ bv,
                float* __restrict__ Qo, float* __restrict__ Ko,
                float* __restrict__ Vo, int K)
{
    int which = blockIdx.z;
    const float* W = which == 0 ? wq : (which == 1 ? wk : wv);
    const float* B = which == 0 ? bq : (which == 1 ? bk : bv);
    float*       C = which == 0 ? Qo : (which == 1 ? Ko : Vo);
    gemm_tile(A, W, B, nullptr, nullptr, nullptr, C, 512, K, FLAG_BIAS,
              blockIdx.x, blockIdx.y);
}

// ------------------------- PE table + embedding -----------------------------
__global__ void pe_kernel(float* __restrict__ PE)
{
    int i = blockIdx.x * blockDim.x + threadIdx.x;
    if (i >= LMAX * D_MODEL) return;
    int d = i & 511;
    int l = i >> 9;
    int kk = d >> 1;
    float prod = (float)(2 * kk) * -0.017988946039015984f;
    float divf = (float)exp((double)prod);
    float angf = (float)l * divf;
    PE[i] = (d & 1) ? (float)cos((double)angf) : (float)sin((double)angf);
}

__global__ void embed_kernel(const float* __restrict__ xe,
                             const float* __restrict__ w,
                             const float* __restrict__ PE,
                             float* __restrict__ X)
{
    int i = blockIdx.x * blockDim.x + threadIdx.x;
    if (i >= BATCH * LMAX * D_MODEL) return;
    int d = i & 511;
    int l = (i >> 9) & (LMAX - 1);
    int b = i >> 20;
    float acc = 0.f;
    #pragma unroll
    for (int j = 0; j < 3; j++) {
        int ls = l + j - 1;
        if (ls < 0) ls += LMAX; else if (ls >= LMAX) ls -= LMAX;
        const float* xr = xe + ((size_t)b * LMAX + ls) * 2;
        acc += xr[0] * w[d * 6 + j] + xr[1] * w[d * 6 + 3 + j];
    }
    X[i] = acc + PE[i & (LMAX * D_MODEL - 1)];
}

// ------------------------- M = max_j(Q.K_idx) - sum_j(Q.K_idx)/L -------------
__global__ void msample_kernel(const float* __restrict__ Q,
                               const float* __restrict__ K,
                               const int* __restrict__ idx,
                               float* __restrict__ M, int L, int U)
{
    int w    = (blockIdx.x * blockDim.x + threadIdx.x) >> 5;
    int lane = threadIdx.x & 31;
    int total = NROW * L;
    if (w >= total) return;
    int l = w % L;
    int h = (w / L) % NH;
    int b = w / (L * NH);
    const float* qp = Q + ((size_t)b * L + l) * D_MODEL + h * DH;
    float q0 = qp[lane], q1 = qp[lane + 32];
    float mx = -3.4e38f, sm = 0.f;
    #pragma unroll 4
    for (int j = 0; j < U; j++) {
        int ki = idx[l * U + j];
        const float* kp = K + ((size_t)b * L + ki) * D_MODEL + h * DH;
        float p = q0 * kp[lane] + q1 * kp[lane + 32];
        #pragma unroll
        for (int o = 16; o > 0; o >>= 1) p += __shfl_xor_sync(0xffffffffu, p, o);
        mx = fmaxf(mx, p);
        sm += p;
    }
    if (lane == 0) M[((size_t)b * NH + h) * L + l] = mx - sm / (float)L;
}

// ------------------------- top-u selection (set semantics) ------------------
__global__ void topk_kernel(const float* __restrict__ M, int* __restrict__ top,
                            int L, int U)
{
    __shared__ float vals[LMAX];
    __shared__ unsigned char flags[LMAX];
    __shared__ float rv[256];
    __shared__ int   ri[256];
    int row = blockIdx.x;
    int t   = threadIdx.x;
    const float* mrow = M + (size_t)row * L;
    for (int l = t; l < L; l += 256) { vals[l] = mrow[l]; flags[l] = 0; }
    __syncthreads();
    for (int pass = 0; pass < U; pass++) {
        float bv = -3.4e38f; int bi = 0x7fffffff;
        for (int l = t; l < L; l += 256) {
            if (!flags[l]) {
                float v = vals[l];
                if (v > bv || (v == bv && l < bi)) { bv = v; bi = l; }
            }
        }
        rv[t] = bv; ri[t] = bi;
        __syncthreads();
        for (int s = 128; s > 0; s >>= 1) {
            if (t < s) {
                float ov = rv[t + s]; int oi = ri[t + s];
                if (ov > rv[t] || (ov == rv[t] && oi < ri[t])) { rv[t] = ov; ri[t] = oi; }
            }
            __syncthreads();
        }
        if (t == 0) { top[row * UMAX + pass] = ri[0]; flags[ri[0]] = 1; }
        __syncthreads();
    }
}

// ------------------------- V mean over L ------------------------------------
__global__ void vmean_kernel(const float* __restrict__ V, float* __restrict__ vm,
                             int L)
{
    __shared__ float red[256];
    int row = blockIdx.x;
    int b = row / NH, h = row % NH;
    int t = threadIdx.x;
    int e = t & 63, grp = t >> 6;
    float acc = 0.f;
    for (int l = grp; l < L; l += 4)
        acc += V[((size_t)b * L + l) * D_MODEL + h * DH + e];
    red[t] = acc;
    __syncthreads();
    if (t < 64)
        vm[(size_t)row * DH + t] =
            (red[t] + red[t + 64] + red[t + 128] + red[t + 192]) / (float)L;
}

__global__ void ofill_kernel(const float* __restrict__ vm, float* __restrict__ O,
                             int n, int L)
{
    int i = blockIdx.x * blockDim.x + threadIdx.x;
    if (i >= n) return;
    int d = i & 511;
    int b = i / (L * 512);
    O[i] = vm[(b * NH + (d >> 6)) * 64 + (d & 63)];
}

// ------------------------- flash-style attention ----------------------------
__global__ void attn_kernel(const float* __restrict__ Q,
                            const float* __restrict__ K,
                            const float* __restrict__ V,
                            const int* __restrict__ top,
                            float* __restrict__ PM, float* __restrict__ PS,
                            float* __restrict__ PA,
                            int L, int U, int keys)
{
    extern __shared__ float smf[];
    float* qs = smf;
    float* P  = qs + UMAX * APAD;
    float* Kt = P  + UMAX * APAD;
    float* Vt = Kt + 64 * APAD;
    __shared__ int qidx[UMAX];

    int split = blockIdx.x;
    int row   = blockIdx.y;
    int b = row / NH, h = row % NH;
    int t = threadIdx.x, lane = t & 31, w = t >> 5;

    if (t < U) qidx[t] = top[row * UMAX + t];
    __syncthreads();
    for (int p = t; p < U * 64; p += 256) {
        int j = p >> 6, e = p & 63;
        qs[j * APAD + e] = Q[((size_t)(b * L + qidx[j])) * D_MODEL + h * DH + e];
    }

    float m0[5], s0[5], a0[5], a1[5];
    #pragma unroll
    for (int r = 0; r < 5; r++) { m0[r] = -3.4e38f; s0[r] = 0.f; a0[r] = 0.f; a1[r] = 0.f; }
    __syncthreads();

    int base0 = split * keys;
    int ntile = keys >> 6;
    for (int tl = 0; tl < ntile; tl++) {
        int kb = base0 + (tl << 6);
        for (int i = t; i < 1024; i += 256) {
            int r = i >> 4, c = (i & 15) << 2;
            size_t gi = ((size_t)(b * L + kb + r)) * D_MODEL + h * DH + c;
            float4 kv = *(const float4*)(K + gi);
            float* dk = &Kt[r * APAD + c];
            dk[0] = kv.x; dk[1] = kv.y; dk[2] = kv.z; dk[3] = kv.w;
            float4 vv = *(const float4*)(V + gi);
            float* dv = &Vt[r * APAD + c];
            dv[0] = vv.x; dv[1] = vv.y; dv[2] = vv.z; dv[3] = vv.w;
        }
        __syncthreads();

        {
            float d0[5], d1[5];
            #pragma unroll
            for (int r = 0; r < 5; r++) { d0[r] = 0.f; d1[r] = 0.f; }
            const float* k0 = &Kt[lane * APAD];
            const float* k1 = &Kt[(lane + 32) * APAD];
            #pragma unroll 8
            for (int e = 0; e < 64; e++) {
                float ke0 = k0[e], ke1 = k1[e];
                #pragma unroll
                for (int r = 0; r < 5; r++) {
                    float qe = qs[(w + (r << 3)) * APAD + e];
                    d0[r] += qe * ke0;
                    d1[r] += qe * ke1;
                }
            }
            #pragma unroll
            for (int r = 0; r < 5; r++) {
                int j = w + (r << 3);
                if (j < U) {
                    P[j * APAD + lane]      = d0[r] * 0.125f;
                    P[j * APAD + lane + 32] = d1[r] * 0.125f;
                }
            }
        }
        __syncwarp();

        #pragma unroll
        for (int r = 0; r < 5; r++) {
            int j = w + (r << 3);
            if (j >= U) break;
            float v0 = P[j * APAD + lane], v1 = P[j * APAD + lane + 32];
            float tm = fmaxf(v0, v1);
            #pragma unroll
            for (int o = 16; o > 0; o >>= 1)
                tm = fmaxf(tm, __shfl_xor_sync(0xffffffffu, tm, o));
            float nm = fmaxf(m0[r], tm);
            float p0 = expf(v0 - nm), p1 = expf(v1 - nm);
            float ts = p0 + p1;
            #pragma unroll
            for (int o = 16; o > 0; o >>= 1)
                ts += __shfl_xor_sync(0xffffffffu, ts, o);
            float al = expf(m0[r] - nm);
            s0[r] = s0[r] * al + ts;
            a0[r] *= al; a1[r] *= al;
            m0[r] = nm;
            P[j * APAD + lane]      = p0;
            P[j * APAD + lane + 32] = p1;
        }
        __syncthreads();

        #pragma unroll 4
        for (int k = 0; k < 64; k++) {
            float ve0 = Vt[k * APAD + lane];
            float ve1 = Vt[k * APAD + lane + 32];
            #pragma unroll
            for (int r = 0; r < 5; r++) {
                float pk = P[(w + (r << 3)) * APAD + k];
                a0[r] += pk * ve0;
                a1[r] += pk * ve1;
            }
        }
        __syncthreads();
    }

    #pragma unroll
    for (int r = 0; r < 5; r++) {
        int j = w + (r << 3);
        if (j >= U) break;
        int pidx = (split * NROW + row) * UMAX + j;
        if (lane == 0) { PM[pidx] = m0[r]; PS[pidx] = s0[r]; }
        PA[(size_t)pidx * 64 + lane]      = a0[r];
        PA[(size_t)pidx * 64 + lane + 32] = a1[r];
    }
}

__global__ void attn_merge(const float* __restrict__ PM,
                           const float* __restrict__ PS,
                           const float* __restrict__ PA,
                           const int* __restrict__ top,
                           float* __restrict__ O, int L, int U, int nsplit)
{
    int gw = (blockIdx.x * blockDim.x + threadIdx.x) >> 5;
    int lane = threadIdx.x & 31;
    if (gw >= NROW * U) return;
    int row = gw / U, j = gw % U;
    int b = row / NH, h = row % NH;
    float M = -3.4e38f;
    for (int i = 0; i < nsplit; i++)
        M = fmaxf(M, PM[(i * NROW + row) * UMAX + j]);
    float s = 0.f, acc0 = 0.f, acc1 = 0.f;
    for (int i = 0; i < nsplit; i++) {
        int pidx = (i * NROW + row) * UMAX + j;
        float sc = expf(PM[pidx] - M);
        s    += PS[pidx] * sc;
        acc0 += PA[(size_t)pidx * 64 + lane] * sc;
        acc1 += PA[(size_t)pidx * 64 + lane + 32] * sc;
    }
    float inv = 1.f / s;
    int qi = top[row * UMAX + j];
    size_t o = ((size_t)(b * L + qi)) * D_MODEL + h * DH;
    O[o + lane]      = acc0 * inv;
    O[o + lane + 32] = acc1 * inv;
}

// ------------------------- LayerNorm (two-pass variance) --------------------
__global__ void ln_kernel(const float* __restrict__ X, const float* __restrict__ g,
                          const float* __restrict__ b, float* __restrict__ Y)
{
    __shared__ float s1[4], s2[4];
    int row = blockIdx.x, t = threadIdx.x;
    const float4 v = ((const float4*)(X + (size_t)row * D_MODEL))[t];
    float s = v.x + v.y + v.z + v.w;
    #pragma unroll
    for (int o = 16; o > 0; o >>= 1) s += __shfl_xor_sync(0xffffffffu, s, o);
    if ((t & 31) == 0) s1[t >> 5] = s;
    __syncthreads();
    float mean = (s1[0] + s1[1] + s1[2] + s1[3]) * (1.f / 512.f);
    float dx = v.x - mean, dy = v.y - mean, dz = v.z - mean, dw = v.w - mean;
    float ss = dx * dx + dy * dy + dz * dz + dw * dw;
    #pragma unroll
    for (int o = 16; o > 0; o >>= 1) ss += __shfl_xor_sync(0xffffffffu, ss, o);
    if ((t & 31) == 0) s2[t >> 5] = ss;
    __syncthreads();
    float var = (s2[0] + s2[1] + s2[2] + s2[3]) * (1.f / 512.f);
    float inv = 1.f / sqrtf(var + 1e-5f);
    const float4 g4 = ((const float4*)g)[t];
    const float4 b4 = ((const float4*)b)[t];
    float4 o;
    o.x = dx * inv * g4.x + b4.x;
    o.y = dy * inv * g4.y + b4.y;
    o.z = dz * inv * g4.z + b4.z;
    o.w = dw * inv * g4.w + b4.w;
    ((float4*)(Y + (size_t)row * D_MODEL))[t] = o;
}

// ------------------------- conv-distill helpers -----------------------------
__global__ void wtrans_kernel(const float* __restrict__ cv, float* __restrict__ WC)
{
    int i = blockIdx.x * blockDim.x + threadIdx.x;
    if (i >= D_MODEL * 3 * D_MODEL) return;
    int n = i / 1536, k = i % 1536;
    int j = k / 512, c = k % 512;
    WC[i] = cv[(size_t)n * 1536 + c * 3 + j];
}

__global__ void xcat_kernel(const float* __restrict__ X, float* __restrict__ XC,
                            int L)
{
    int m = blockIdx.x;
    int t = threadIdx.x;
    int b = m / L, l = m % L;
    float4* dst = (float4*)(XC + (size_t)m * 1536);
    #pragma unroll
    for (int r = 0; r < 3; r++) {
        int ls = l + r - 1;
        if (ls < 0) ls += L; else if (ls >= L) ls -= L;
        dst[r * 128 + t] = ((const float4*)(X + ((size_t)b * L + ls) * 512))[t];
    }
}

__global__ void pool_kernel(const float* __restrict__ Y, float* __restrict__ X,
                            int L)
{
    int Lh = L >> 1;
    int i = blockIdx.x * blockDim.x + threadIdx.x;
    if (i >= BATCH * Lh * 512) return;
    int d = i & 511;
    int m = (i >> 9) % Lh;
    int b = i / (Lh * 512);
    const float* yb = Y + (size_t)b * L * 512 + d;
    float v = fmaxf(yb[(size_t)(2 * m) * 512], yb[(size_t)(2 * m + 1) * 512]);
    if (m > 0) v = fmaxf(v, yb[(size_t)(2 * m - 1) * 512]);
    X[i] = v;
}

// ---------------------------------------------------------------------------
extern "C" void kernel_launch(void* const* d_in, const int* in_sizes, int n_in,
                              void* d_out, int out_size)
{
    (void)in_sizes; (void)n_in; (void)out_size;
    const float* x_enc = (const float*)d_in[0];
    const float* emb_w = (const float*)d_in[1];
    const float* Wq  = (const float*)d_in[2];
    const float* bq  = (const float*)d_in[3];
    const float* Wk  = (const float*)d_in[4];
    const float* bk  = (const float*)d_in[5];
    const float* Wv  = (const float*)d_in[6];
    const float* bv  = (const float*)d_in[7];
    const float* Wo  = (const float*)d_in[8];
    const float* bo  = (const float*)d_in[9];
    const float* ln1g = (const float*)d_in[10];
    const float* ln1b = (const float*)d_in[11];
    const float* W1  = (const float*)d_in[12];
    const float* b1  = (const float*)d_in[13];
    const float* W2  = (const float*)d_in[14];
    const float* b2  = (const float*)d_in[15];
    const float* ln2g = (const float*)d_in[16];
    const float* ln2b = (const float*)d_in[17];
    const float* cvw = (const float*)d_in[18];
    const float* cvb = (const float*)d_in[19];
    const float* bng = (const float*)d_in[20];
    const float* bnb = (const float*)d_in[21];
    const float* ngp = (const float*)d_in[22];
    const float* nbp = (const float*)d_in[23];

    float *X, *XN, *Yb, *Qb, *Kb, *Vb, *Ob, *H1b, *XC, *CVb, *WCb, *Mb, *VMb;
    float *PEb, *PMb, *PSb, *PAb;
    int *IDXb, *TOPb;
    cudaGetSymbolAddress((void**)&X,   g_X);
    cudaGetSymbolAddress((void**)&XN,  g_XN);
    cudaGetSymbolAddress((void**)&Yb,  g_Y);
    cudaGetSymbolAddress((void**)&Qb,  g_Q);
    cudaGetSymbolAddress((void**)&Kb,  g_K);
    cudaGetSymbolAddress((void**)&Vb,  g_V);
    cudaGetSymbolAddress((void**)&Ob,  g_O);
    cudaGetSymbolAddress((void**)&H1b, g_H1);
    cudaGetSymbolAddress((void**)&XC,  g_XC);
    cudaGetSymbolAddress((void**)&CVb, g_CV);
    cudaGetSymbolAddress((void**)&WCb, g_WC);
    cudaGetSymbolAddress((void**)&PEb, g_PE);
    cudaGetSymbolAddress((void**)&Mb,  g_M);
    cudaGetSymbolAddress((void**)&VMb, g_VM);
    cudaGetSymbolAddress((void**)&PMb, g_PM);
    cudaGetSymbolAddress((void**)&PSb, g_PS);
    cudaGetSymbolAddress((void**)&PAb, g_PA);
    cudaGetSymbolAddress((void**)&IDXb, g_IDX);
    cudaGetSymbolAddress((void**)&TOPb, g_TOP);

    const int attn_smem = (UMAX * APAD * 2 + 64 * APAD * 2) * 4;
    cudaFuncSetAttribute(attn_kernel,
                         cudaFuncAttributeMaxDynamicSharedMemorySize, attn_smem);
    cudaFuncSetAttribute(sgemm_kernel,
                         cudaFuncAttributeMaxDynamicSharedMemorySize, GEMM_SMEM);
    cudaFuncSetAttribute(qkv_kernel,
                         cudaFuncAttributeMaxDynamicSharedMemorySize, GEMM_SMEM);

    pe_kernel<<<(LMAX * D_MODEL + 255) / 256, 256>>>(PEb);
    {
        int total = BATCH * LMAX * D_MODEL;
        embed_kernel<<<(total + 255) / 256, 256>>>(x_enc, emb_w, PEb, X);
    }

    int L = LMAX;
    for (int layer = 0; layer < 3; layer++) {
        int U = 5 * (int)ceil(log((double)L));   // 40, 35, 35
        if (U > L) U = L;
        int Mrows = BATCH * L;
        dim3 gg(D_MODEL / 128, Mrows / 128);

        const float* wq = Wq + (size_t)layer * 512 * 512;
        const float* wk = Wk + (size_t)layer * 512 * 512;
        const float* wv = Wv + (size_t)layer * 512 * 512;
        const float* wo = Wo + (size_t)layer * 512 * 512;
        const float* w1 = W1 + (size_t)layer * 512 * 512;
        const float* w2 = W2 + (size_t)layer * 512 * 512;

        {
            dim3 gq(D_MODEL / 128, Mrows / 128, 3);
            qkv_kernel<<<gq, 256, GEMM_SMEM>>>(X, wq, wk, wv,
                                               bq + layer * 512, bk + layer * 512,
                                               bv + layer * 512, Qb, Kb, Vb, 512);
        }

        uint32_t f0, f1, k2a, k2b;
        threefry2x32(0u, 42u, 0u, (uint32_t)layer, &f0, &f1);
        threefry2x32(f0, f1, 0u, 1u, &k2a, &k2b);
        int nidx = L * U;
        idx_kernel<<<(nidx + 255) / 256, 256>>>(k2a, k2b, nidx, (unsigned)(L - 1), IDXb);

        int warps = NROW * L;
        msample_kernel<<<(warps * 32 + 255) / 256, 256>>>(Qb, Kb, IDXb, Mb, L, U);
        topk_kernel<<<NROW, 256>>>(Mb, TOPb, L, U);
        vmean_kernel<<<NROW, 256>>>(Vb, VMb, L);
        ofill_kernel<<<(Mrows * 512 + 255) / 256, 256>>>(VMb, Ob, Mrows * 512, L);

        {
            int keys = 512;
            int nsplit = L / keys;
            dim3 ag(nsplit, NROW);
            attn_kernel<<<ag, 256, attn_smem>>>(Qb, Kb, Vb, TOPb,
                                                PMb, PSb, PAb, L, U, keys);
            int mw = NROW * U;
            attn_merge<<<(mw * 32 + 255) / 256, 256>>>(PMb, PSb, PAb, TOPb,
                                                       Ob, L, U, nsplit);
        }

        sgemm_kernel<<<gg, 256, GEMM_SMEM>>>(Ob, wo, bo + layer * 512, X,
                                             nullptr, nullptr, Yb, 512, 512,
                                             FLAG_BIAS | FLAG_RES);
        ln_kernel<<<Mrows, 128>>>(Yb, ln1g + layer * 512, ln1b + layer * 512, XN);
        sgemm_kernel<<<gg, 256, GEMM_SMEM>>>(XN, w1, b1 + layer * 512, nullptr,
                                             nullptr, nullptr, H1b, 512, 512,
                                             FLAG_BIAS | FLAG_GELU);
        sgemm_kernel<<<gg, 256, GEMM_SMEM>>>(H1b, w2, b2 + layer * 512, XN,
                                             nullptr, nullptr, Yb, 512, 512,
                                             FLAG_BIAS | FLAG_RES);
        ln_kernel<<<Mrows, 128>>>(Yb, ln2g + layer * 512, ln2b + layer * 512, X);

        if (layer < 2) {
            wtrans_kernel<<<(512 * 1536 + 255) / 256, 256>>>(cvw + (size_t)layer * 512 * 1536, WCb);
            xcat_kernel<<<Mrows, 128>>>(X, XC, L);
            sgemm_kernel<<<gg, 256, GEMM_SMEM>>>(XC, WCb, cvb + layer * 512, nullptr,
                                                 bng + layer * 512, bnb + layer * 512,
                                                 CVb, 512, 1536, FLAG_BIAS | FLAG_ELU);
            int Lh = L / 2;
            pool_kernel<<<(BATCH * Lh * 512 + 255) / 256, 256>>>(CVb, X, L);
            L = Lh;
        }
    }

    ln_kernel<<<BATCH * L, 128>>>(X, ngp, nbp, (float*)d_out);
}